// round 14
// baseline (speedup 1.0000x reference)
#include <cuda_runtime.h>
#include <cuda_fp16.h>
#include <math.h>
#include <stdint.h>

// Problem constants
#define B_SZ 2
#define S_SZ 2048
#define HID 4096
#define NH 32
#define HD 128
#define TOK (B_SZ * S_SZ)          // 4096 tokens
#define PROJ3 (3 * HID)            // 12288

// Scratch (static device globals — allocation-free rule)
__device__ __half g_Ah[(size_t)TOK * HID];
__device__ __half g_Wp[(size_t)PROJ3 * HID];
__device__ __half g_Wo[(size_t)HID * HID];
__device__ __half g_Xh[(size_t)TOK * HID];
// head-major fp16 attention operands [b*NH+h][s][d]
__device__ __half g_Qh[(size_t)TOK * HID];
__device__ __half g_Kh[(size_t)TOK * HID];
__device__ __half g_Vh[(size_t)TOK * HID];

// ---------------------------------------------------------------------------
// Inline PTX helpers
// ---------------------------------------------------------------------------
__device__ __forceinline__ uint32_t smem_u32(const void* p) {
    uint32_t a;
    asm("{ .reg .u64 t; cvta.to.shared.u64 t, %1; cvt.u32.u64 %0, t; }" : "=r"(a) : "l"(p));
    return a;
}
__device__ __forceinline__ void cp16(uint32_t dst, const void* src) {
    asm volatile("cp.async.cg.shared.global [%0], [%1], 16;" :: "r"(dst), "l"(src) : "memory");
}
__device__ __forceinline__ void cp_commit() { asm volatile("cp.async.commit_group;" ::: "memory"); }
template <int N>
__device__ __forceinline__ void cp_wait() {
    asm volatile("cp.async.wait_group %0;" :: "n"(N) : "memory");
}
__device__ __forceinline__ void ldsm4(uint32_t r[4], uint32_t addr) {
    asm volatile("ldmatrix.sync.aligned.m8n8.x4.shared.b16 {%0,%1,%2,%3}, [%4];"
                 : "=r"(r[0]), "=r"(r[1]), "=r"(r[2]), "=r"(r[3]) : "r"(addr));
}
__device__ __forceinline__ void ldsm4t(uint32_t r[4], uint32_t addr) {
    asm volatile("ldmatrix.sync.aligned.m8n8.x4.trans.shared.b16 {%0,%1,%2,%3}, [%4];"
                 : "=r"(r[0]), "=r"(r[1]), "=r"(r[2]), "=r"(r[3]) : "r"(addr));
}
__device__ __forceinline__ void mma16816(float c[4], const uint32_t a[4], const uint32_t b[2]) {
    asm volatile(
        "mma.sync.aligned.m16n8k16.row.col.f32.f16.f16.f32 "
        "{%0,%1,%2,%3}, {%4,%5,%6,%7}, {%8,%9}, {%0,%1,%2,%3};"
        : "+f"(c[0]), "+f"(c[1]), "+f"(c[2]), "+f"(c[3])
        : "r"(a[0]), "r"(a[1]), "r"(a[2]), "r"(a[3]), "r"(b[0]), "r"(b[1]));
}
__device__ __forceinline__ uint32_t packh2(float a, float b) {
    __half2 h = __floats2half2_rn(a, b);
    return *(uint32_t*)&h;
}

// ---------------------------------------------------------------------------
// fp32 -> fp16 round. 8 elements/thread.
// ---------------------------------------------------------------------------
__global__ void conv_f16(const float* __restrict__ x, __half* __restrict__ y, int n8)
{
    int i = blockIdx.x * blockDim.x + threadIdx.x;
    if (i >= n8) return;
    const float4* xp = (const float4*)x + (size_t)i * 2;
    float4 a = xp[0], b = xp[1];
    float v[8] = {a.x, a.y, a.z, a.w, b.x, b.y, b.z, b.w};
    __half h[8];
#pragma unroll
    for (int j = 0; j < 8; j++) h[j] = __float2half_rn(v[j]);
    *((uint4*)y + i) = *(const uint4*)h;
}

// ---------------------------------------------------------------------------
// GEMM config: CTA 128x128, BK=64, 2-stage cp.async, 128 threads
// (4 warps 2x2, warp tile 64x64 — balanced ldsm:MMA), 3 CTAs/SM.
// Inner loop streams A fragments (af live 4 regs) against resident bf[16]
// to minimize register liveness (avoid the R13 spill).
// ---------------------------------------------------------------------------
#define BM 128
#define BN 128
#define BK 64
#define PADK 72                        // halves per smem row (64 + 8 pad)
#define TILEA (128 * PADK * 2)         // 18432 B
#define STAGEB (2 * TILEA)             // 36864 B
#define GEMM_SMEM (2 * STAGEB)         // 73728 B (2 stages)

#define GEMM_MAINLOOP64(Aptr, Bptr, Kval)                                        \
    const int NCH = (Kval) >> 6;                                                 \
    auto load_chunk = [&](int cc, int stg) {                                     \
        const uint32_t sb = sbase + stg * STAGEB;                                \
        const int kc = cc * BK;                                                  \
        _Pragma("unroll")                                                        \
        for (int i = 0; i < 8; i++) {                                            \
            int op = tid + i * 128;       /* 0..1023 */                          \
            int row = op >> 3;                                                   \
            int ck = op & 7;                                                     \
            uint32_t soff = (uint32_t)(row * PADK * 2 + ck * 16);                \
            cp16(sb + soff, (Aptr) + (size_t)(m0 + row) * (Kval) + kc + ck * 8); \
            cp16(sb + TILEA + soff,                                              \
                 (Bptr) + (size_t)(n0 + row) * (Kval) + kc + ck * 8);            \
        }                                                                        \
        cp_commit();                                                             \
    };                                                                           \
    load_chunk(0, 0);                                                            \
    const int a_row = (lane & 15);                                               \
    const int a_col = ((lane >> 4) & 1) * 8;                                     \
    const int b_row = (lane & 7) + ((lane & 16) ? 8 : 0);                        \
    const int b_col = ((lane & 8) ? 8 : 0);                                      \
    for (int cch = 0; cch < NCH; cch++) {                                        \
        cp_wait<0>();                                                            \
        __syncthreads();                                                         \
        if (cch + 1 < NCH) load_chunk(cch + 1, (cch + 1) & 1);                   \
        const uint32_t sA = sbase + (cch & 1) * STAGEB;                          \
        const uint32_t sB = sA + TILEA;                                          \
        _Pragma("unroll")                                                        \
        for (int s = 0; s < 4; s++) {                                            \
            uint32_t bf[16];                                                     \
            _Pragma("unroll")                                                    \
            for (int j2 = 0; j2 < 4; j2++) {                                     \
                int row = wn * 64 + j2 * 16 + b_row;                             \
                ldsm4(&bf[j2 * 4],                                               \
                      sB + (uint32_t)((row * PADK + s * 16 + b_col) * 2));       \
            }                                                                    \
            _Pragma("unroll")                                                    \
            for (int i = 0; i < 4; i++) {                                        \
                uint32_t af[4];                                                  \
                int row = wm * 64 + i * 16 + a_row;                              \
                ldsm4(af, sA + (uint32_t)((row * PADK + s * 16 + a_col) * 2));   \
                _Pragma("unroll")                                                \
                for (int j = 0; j < 8; j++)                                      \
                    mma16816(c[i][j], af, &bf[j * 2]);                           \
            }                                                                    \
        }                                                                        \
    }

// ---------------------------------------------------------------------------
// Plain GEMM: C[M,N] = A @ B^T, fp32 out (O-projection).
// ---------------------------------------------------------------------------
__global__ __launch_bounds__(128, 3)
void gemm_f16(const __half* __restrict__ Ah, const __half* __restrict__ Bh,
              float* __restrict__ C, int N, int K)
{
    extern __shared__ char smraw[];
    const uint32_t sbase = smem_u32(smraw);

    const int tid = threadIdx.x;
    const int wid = tid >> 5;
    const int lane = tid & 31;
    const int wm = wid >> 1;          // 0..1 (64 rows)
    const int wn = wid & 1;           // 0..1 (64 cols)
    const int m0 = blockIdx.y * BM;
    const int n0 = blockIdx.x * BN;

    float c[4][8][4];
#pragma unroll
    for (int i = 0; i < 4; i++)
#pragma unroll
        for (int j = 0; j < 8; j++)
#pragma unroll
            for (int q = 0; q < 4; q++) c[i][j][q] = 0.f;

    GEMM_MAINLOOP64(Ah, Bh, K)

    const int g = lane >> 2;
    const int tq = lane & 3;
#pragma unroll
    for (int i = 0; i < 4; i++) {
        int row0 = m0 + wm * 64 + i * 16 + g;
#pragma unroll
        for (int j = 0; j < 8; j++) {
            int col = n0 + wn * 64 + j * 8 + tq * 2;
            float2 v0 = {c[i][j][0], c[i][j][1]};
            float2 v1 = {c[i][j][2], c[i][j][3]};
            *(float2*)&C[(size_t)row0 * N + col] = v0;
            *(float2*)&C[(size_t)(row0 + 8) * N + col] = v1;
        }
    }
}

// ---------------------------------------------------------------------------
// QKV GEMM with fused RoPE + fp16 head-major epilogue.
// ---------------------------------------------------------------------------
#define SCPAD 132   // fp32 row stride in epilogue smem (128*132*4 = 67584 <= 73728)

__global__ __launch_bounds__(128, 3)
void gemm_qkv(const __half* __restrict__ Ah, const __half* __restrict__ Bh,
              const int* __restrict__ positions,
              __half* __restrict__ Qh, __half* __restrict__ Kh,
              __half* __restrict__ Vh, int N, int K)
{
    extern __shared__ char smraw[];
    const uint32_t sbase = smem_u32(smraw);

    const int tid = threadIdx.x;
    const int wid = tid >> 5;
    const int lane = tid & 31;
    const int wm = wid >> 1;
    const int wn = wid & 1;
    const int m0 = blockIdx.y * BM;
    const int n0 = blockIdx.x * BN;

    float c[4][8][4];
#pragma unroll
    for (int i = 0; i < 4; i++)
#pragma unroll
        for (int j = 0; j < 8; j++)
#pragma unroll
            for (int q = 0; q < 4; q++) c[i][j][q] = 0.f;

    GEMM_MAINLOOP64(Ah, Bh, K)

    // ---- fused epilogue: stage fp32 tile in smem ----
    __syncthreads();
    float* sc = (float*)smraw;       // [128][SCPAD]

    const int g = lane >> 2;
    const int tq = lane & 3;
#pragma unroll
    for (int i = 0; i < 4; i++) {
        int r0 = wm * 64 + i * 16 + g;
#pragma unroll
        for (int j = 0; j < 8; j++) {
            int col = wn * 64 + j * 8 + tq * 2;
            *(float2*)&sc[r0 * SCPAD + col] = make_float2(c[i][j][0], c[i][j][1]);
            *(float2*)&sc[(r0 + 8) * SCPAD + col] = make_float2(c[i][j][2], c[i][j][3]);
        }
    }
    __syncthreads();

    const int region = n0 >> 12;
    const int h = (n0 & 4095) >> 7;
    const float qscale = (region == 0) ? 0.08838834764831845f : 1.0f;
    __half* outp = (region == 0) ? Qh : (region == 1 ? Kh : Vh);

    // 128 threads: 16 col-threads x 8 row-threads; 16 row iterations
    const int i0 = (tid & 15) * 4;
    const int rbase = tid >> 4;       // 0..7

#pragma unroll 1
    for (int rr = 0; rr < 16; rr++) {
        int row = rbase + rr * 8;
        int t = m0 + row;
        int pos = positions[t];
        int bb = t >> 11;
        int ss = t & 2047;
        __half* dp = outp + ((size_t)(bb * NH + h) * S_SZ + ss) * HD;

        float r1v[4], r2v[4];
#pragma unroll
        for (int ii = 0; ii < 4; ii++) {
            int i = i0 + ii;
            float x1 = sc[row * SCPAD + i];
            float x2 = sc[row * SCPAD + i + 64];
            float cs, sn;
            if (region < 2) {
                float f = (float)pos * exp2f(-(float)i * (13.287712379549449f / 64.0f));
                sincosf(f, &sn, &cs);
            } else { cs = 1.f; sn = 0.f; }
            r1v[ii] = (x1 * cs - x2 * sn) * qscale;
            r2v[ii] = (x2 * cs + x1 * sn) * qscale;
        }
        *(uint32_t*)&dp[i0]     = packh2(r1v[0], r1v[1]);
        *(uint32_t*)&dp[i0 + 2] = packh2(r1v[2], r1v[3]);
        *(uint32_t*)&dp[i0 + 64] = packh2(r2v[0], r2v[1]);
        *(uint32_t*)&dp[i0 + 66] = packh2(r2v[2], r2v[3]);
    }
}

// ---------------------------------------------------------------------------
// HMMA flash attention, causal. Br=128 (8 warps x 16 rows), Bc=128.
// (unchanged from R12/R13 — best known)
// ---------------------------------------------------------------------------
#define ATT_PAD 136
#define KVROWB (ATT_PAD * 2)            // 272 bytes
#define KTILE2 (128 * KVROWB)           // 34816
#define ASTG (2 * KTILE2)               // K, V = 69632
#define ATT_SMEM (2 * ASTG)             // 139264

__global__ __launch_bounds__(256, 1)
void flash_attn_hmma(const __half* __restrict__ Qh, const __half* __restrict__ Kh,
                     const __half* __restrict__ Vh, __half* __restrict__ Xh)
{
    extern __shared__ char smraw[];
    const uint32_t sbase = smem_u32(smraw);

    const int tid = threadIdx.x;
    const int wid = tid >> 5;
    const int lane = tid & 31;
    const int g = lane >> 2;
    const int tq = lane & 3;

    const int qb = 15 - (int)blockIdx.x;
    const int bh = blockIdx.y;
    const int b = bh >> 5;
    const int h = bh & 31;
    const size_t hb = (size_t)bh * S_SZ * HD;
    const int row0 = qb * 128;
    const int wr = wid * 16;
    const int nkb = qb + 1;

    uint32_t qhf[8][4];
    {
        const __half* qsrc = Qh + hb + (size_t)row0 * HD;
#pragma unroll
        for (int i = 0; i < 8; i++) {
            int op = tid + i * 256;
            int r = op >> 4;
            int ck = op & 15;
            cp16(sbase + (uint32_t)(r * KVROWB + ck * 16), qsrc + (size_t)r * HD + ck * 8);
        }
        cp_commit();
        cp_wait<0>();
        __syncthreads();
#pragma unroll
        for (int ks = 0; ks < 8; ks++) {
            uint32_t off = (uint32_t)((wr + (lane & 15)) * KVROWB +
                                      (ks * 16 + ((lane >> 4) << 3)) * 2);
            ldsm4(qhf[ks], sbase + off);
        }
        __syncthreads();
    }

    float o[16][4];
#pragma unroll
    for (int j = 0; j < 16; j++)
#pragma unroll
        for (int q = 0; q < 4; q++) o[j][q] = 0.f;
    float m_old0 = -1e30f, m_old1 = -1e30f, l0 = 0.f, l1 = 0.f;

    auto kvload = [&](int kb, int stg) {
        const uint32_t sb = sbase + stg * ASTG;
        const size_t src0 = hb + (size_t)kb * 128 * HD;
#pragma unroll
        for (int i = 0; i < 8; i++) {
            int op = tid + i * 256;
            int r = op >> 4;
            int ck = op & 15;
            uint32_t soff = (uint32_t)(r * KVROWB + ck * 16);
            size_t goff = src0 + (size_t)r * HD + ck * 8;
            cp16(sb + soff, Kh + goff);
            cp16(sb + KTILE2 + soff, Vh + goff);
        }
        cp_commit();
    };

    kvload(0, 0);

    const int r_g = row0 + wr + g;

    for (int kb = 0; kb < nkb; kb++) {
        if (kb + 1 < nkb) kvload(kb + 1, (kb + 1) & 1);
        else cp_commit();
        cp_wait<1>();
        __syncthreads();

        const uint32_t sK = sbase + (kb & 1) * ASTG;
        const uint32_t sV = sK + KTILE2;

        float s[16][4];
#pragma unroll
        for (int j = 0; j < 16; j++)
#pragma unroll
            for (int q = 0; q < 4; q++) s[j][q] = 0.f;

#pragma unroll
        for (int ks = 0; ks < 8; ks++) {
            uint32_t bk[32];
#pragma unroll
            for (int j2 = 0; j2 < 8; j2++) {
                int r = j2 * 16 + (lane & 7) + ((lane & 16) ? 8 : 0);
                uint32_t off = (uint32_t)(r * KVROWB + (ks * 16 + ((lane & 8) ? 8 : 0)) * 2);
                ldsm4(&bk[j2 * 4], sK + off);
            }
#pragma unroll
            for (int j = 0; j < 16; j++) mma16816(s[j], qhf[ks], &bk[j * 2]);
        }

        const int kv0 = kb * 128;
        if (kv0 + 127 > row0 + wr) {
#pragma unroll
            for (int j = 0; j < 16; j++) {
                int cc = kv0 + j * 8 + 2 * tq;
                if (cc > r_g) s[j][0] = -1e30f;
                if (cc + 1 > r_g) s[j][1] = -1e30f;
                if (cc > r_g + 8) s[j][2] = -1e30f;
                if (cc + 1 > r_g + 8) s[j][3] = -1e30f;
            }
        }

        float mx0 = -1e30f, mx1 = -1e30f;
#pragma unroll
        for (int j = 0; j < 16; j++) {
            mx0 = fmaxf(mx0, fmaxf(s[j][0], s[j][1]));
            mx1 = fmaxf(mx1, fmaxf(s[j][2], s[j][3]));
        }
        mx0 = fmaxf(mx0, __shfl_xor_sync(0xffffffffu, mx0, 1));
        mx0 = fmaxf(mx0, __shfl_xor_sync(0xffffffffu, mx0, 2));
        mx1 = fmaxf(mx1, __shfl_xor_sync(0xffffffffu, mx1, 1));
        mx1 = fmaxf(mx1, __shfl_xor_sync(0xffffffffu, mx1, 2));

        float mn0 = fmaxf(m_old0, mx0);
        float mn1 = fmaxf(m_old1, mx1);
        float a0 = __expf(m_old0 - mn0);
        float a1 = __expf(m_old1 - mn1);

        float sum0 = 0.f, sum1 = 0.f;
        uint32_t pa[8][4];
#pragma unroll
        for (int ks = 0; ks < 8; ks++) {
            float p00 = __expf(s[2 * ks][0] - mn0);
            float p01 = __expf(s[2 * ks][1] - mn0);
            float p02 = __expf(s[2 * ks][2] - mn1);
            float p03 = __expf(s[2 * ks][3] - mn1);
            float p10 = __expf(s[2 * ks + 1][0] - mn0);
            float p11 = __expf(s[2 * ks + 1][1] - mn0);
            float p12 = __expf(s[2 * ks + 1][2] - mn1);
            float p13 = __expf(s[2 * ks + 1][3] - mn1);
            sum0 += p00 + p01 + p10 + p11;
            sum1 += p02 + p03 + p12 + p13;
            pa[ks][0] = packh2(p00, p01);
            pa[ks][1] = packh2(p02, p03);
            pa[ks][2] = packh2(p10, p11);
            pa[ks][3] = packh2(p12, p13);
        }
        sum0 += __shfl_xor_sync(0xffffffffu, sum0, 1);
        sum0 += __shfl_xor_sync(0xffffffffu, sum0, 2);
        sum1 += __shfl_xor_sync(0xffffffffu, sum1, 1);
        sum1 += __shfl_xor_sync(0xffffffffu, sum1, 2);

        l0 = l0 * a0 + sum0;
        l1 = l1 * a1 + sum1;
        m_old0 = mn0;
        m_old1 = mn1;

#pragma unroll
        for (int j = 0; j < 16; j++) {
            o[j][0] *= a0; o[j][1] *= a0;
            o[j][2] *= a1; o[j][3] *= a1;
        }

#pragma unroll
        for (int ks = 0; ks < 8; ks++) {
#pragma unroll
            for (int jj = 0; jj < 8; jj++) {
                int krow = ks * 16 + (lane & 15);
                uint32_t off = (uint32_t)(krow * KVROWB + (jj * 16 + ((lane & 16) ? 8 : 0)) * 2);
                uint32_t bv[4];
                ldsm4t(bv, sV + off);
                mma16816(o[jj * 2], pa[ks], &bv[0]);
                mma16816(o[jj * 2 + 1], pa[ks], &bv[2]);
            }
        }
        __syncthreads();
    }

    const float il0 = 1.f / l0;
    const float il1 = 1.f / l1;
    const int tok0 = b * S_SZ + row0 + wr;
#pragma unroll
    for (int j = 0; j < 16; j++) {
        int col = h * HD + j * 8 + 2 * tq;
        size_t i0 = (size_t)(tok0 + g) * HID + col;
        size_t i1 = (size_t)(tok0 + g + 8) * HID + col;
        *(uint32_t*)&Xh[i0] = packh2(o[j][0] * il0, o[j][1] * il0);
        *(uint32_t*)&Xh[i1] = packh2(o[j][2] * il1, o[j][3] * il1);
    }
}

// ---------------------------------------------------------------------------
// Launch
// ---------------------------------------------------------------------------
extern "C" void kernel_launch(void* const* d_in, const int* in_sizes, int n_in,
                              void* d_out, int out_size)
{
    const float* hidden = (const float*)d_in[0];
    const int* positions = (const int*)d_in[1];
    const float* W_pack = (const float*)d_in[2];
    const float* W_o = (const float*)d_in[3];
    float* out = (float*)d_out;

    void* v_ah; cudaGetSymbolAddress(&v_ah, g_Ah);
    void* v_wp; cudaGetSymbolAddress(&v_wp, g_Wp);
    void* v_wo; cudaGetSymbolAddress(&v_wo, g_Wo);
    void* v_xh; cudaGetSymbolAddress(&v_xh, g_Xh);
    void* v_qh; cudaGetSymbolAddress(&v_qh, g_Qh);
    void* v_kh; cudaGetSymbolAddress(&v_kh, g_Kh);
    void* v_vh; cudaGetSymbolAddress(&v_vh, g_Vh);

    cudaFuncSetAttribute(gemm_f16, cudaFuncAttributeMaxDynamicSharedMemorySize, GEMM_SMEM);
    cudaFuncSetAttribute(gemm_qkv, cudaFuncAttributeMaxDynamicSharedMemorySize, GEMM_SMEM);
    cudaFuncSetAttribute(flash_attn_hmma, cudaFuncAttributeMaxDynamicSharedMemorySize, ATT_SMEM);

    // 0) operand prep
    {
        int n8 = TOK * HID / 8;
        conv_f16<<<(n8 + 255) / 256, 256>>>(hidden, (__half*)v_ah, n8);
        int w8 = PROJ3 * HID / 8;
        conv_f16<<<(w8 + 255) / 256, 256>>>(W_pack, (__half*)v_wp, w8);
        int o8 = HID * HID / 8;
        conv_f16<<<(o8 + 255) / 256, 256>>>(W_o, (__half*)v_wo, o8);
    }

    // 1) QKV projection + fused RoPE + fp16 head-major conversion
    {
        dim3 grid(PROJ3 / BN, TOK / BM);  // 96 x 32
        gemm_qkv<<<grid, 128, GEMM_SMEM>>>((const __half*)v_ah, (const __half*)v_wp,
                                           positions,
                                           (__half*)v_qh, (__half*)v_kh, (__half*)v_vh,
                                           PROJ3, HID);
    }

    // 2) Causal attention on tensor cores; writes Xh directly
    {
        dim3 grid(S_SZ / 128, B_SZ * NH);  // 16 x 64
        flash_attn_hmma<<<grid, 256, ATT_SMEM>>>((const __half*)v_qh, (const __half*)v_kh,
                                                 (const __half*)v_vh, (__half*)v_xh);
    }

    // 3) out = attn @ W_o^T
    {
        dim3 grid(HID / BN, TOK / BM);  // 32 x 32
        gemm_f16<<<grid, 128, GEMM_SMEM>>>((const __half*)v_xh, (const __half*)v_wo,
                                           out, HID, HID);
    }
}

// round 15
// speedup vs baseline: 1.0267x; 1.0267x over previous
#include <cuda_runtime.h>
#include <cuda_fp16.h>
#include <math.h>
#include <stdint.h>

// Problem constants
#define B_SZ 2
#define S_SZ 2048
#define HID 4096
#define NH 32
#define HD 128
#define TOK (B_SZ * S_SZ)          // 4096 tokens
#define PROJ3 (3 * HID)            // 12288

// Scratch (static device globals — allocation-free rule)
__device__ __half g_Ah[(size_t)TOK * HID];
__device__ __half g_Wp[(size_t)PROJ3 * HID];
__device__ __half g_Wo[(size_t)HID * HID];
__device__ __half g_Xh[(size_t)TOK * HID];
// head-major fp16 attention operands [b*NH+h][s][d]
__device__ __half g_Qh[(size_t)TOK * HID];
__device__ __half g_Kh[(size_t)TOK * HID];
__device__ __half g_Vh[(size_t)TOK * HID];
// RoPE cos/sin table per (token, pair-index)
__device__ float2 g_rope[(size_t)TOK * 64];

// ---------------------------------------------------------------------------
// Inline PTX helpers
// ---------------------------------------------------------------------------
__device__ __forceinline__ uint32_t smem_u32(const void* p) {
    uint32_t a;
    asm("{ .reg .u64 t; cvta.to.shared.u64 t, %1; cvt.u32.u64 %0, t; }" : "=r"(a) : "l"(p));
    return a;
}
__device__ __forceinline__ void cp16(uint32_t dst, const void* src) {
    asm volatile("cp.async.cg.shared.global [%0], [%1], 16;" :: "r"(dst), "l"(src) : "memory");
}
__device__ __forceinline__ void cp_commit() { asm volatile("cp.async.commit_group;" ::: "memory"); }
template <int N>
__device__ __forceinline__ void cp_wait() {
    asm volatile("cp.async.wait_group %0;" :: "n"(N) : "memory");
}
__device__ __forceinline__ void ldsm4(uint32_t r[4], uint32_t addr) {
    asm volatile("ldmatrix.sync.aligned.m8n8.x4.shared.b16 {%0,%1,%2,%3}, [%4];"
                 : "=r"(r[0]), "=r"(r[1]), "=r"(r[2]), "=r"(r[3]) : "r"(addr));
}
__device__ __forceinline__ void ldsm4t(uint32_t r[4], uint32_t addr) {
    asm volatile("ldmatrix.sync.aligned.m8n8.x4.trans.shared.b16 {%0,%1,%2,%3}, [%4];"
                 : "=r"(r[0]), "=r"(r[1]), "=r"(r[2]), "=r"(r[3]) : "r"(addr));
}
__device__ __forceinline__ void mma16816(float c[4], const uint32_t a[4], const uint32_t b[2]) {
    asm volatile(
        "mma.sync.aligned.m16n8k16.row.col.f32.f16.f16.f32 "
        "{%0,%1,%2,%3}, {%4,%5,%6,%7}, {%8,%9}, {%0,%1,%2,%3};"
        : "+f"(c[0]), "+f"(c[1]), "+f"(c[2]), "+f"(c[3])
        : "r"(a[0]), "r"(a[1]), "r"(a[2]), "r"(a[3]), "r"(b[0]), "r"(b[1]));
}
__device__ __forceinline__ uint32_t packh2(float a, float b) {
    __half2 h = __floats2half2_rn(a, b);
    return *(uint32_t*)&h;
}

// ---------------------------------------------------------------------------
// fp32 -> fp16 round. 8 elements/thread.
// ---------------------------------------------------------------------------
__global__ void conv_f16(const float* __restrict__ x, __half* __restrict__ y, int n8)
{
    int i = blockIdx.x * blockDim.x + threadIdx.x;
    if (i >= n8) return;
    const float4* xp = (const float4*)x + (size_t)i * 2;
    float4 a = xp[0], b = xp[1];
    float v[8] = {a.x, a.y, a.z, a.w, b.x, b.y, b.z, b.w};
    __half h[8];
#pragma unroll
    for (int j = 0; j < 8; j++) h[j] = __float2half_rn(v[j]);
    *((uint4*)y + i) = *(const uint4*)h;
}

// ---------------------------------------------------------------------------
// Build RoPE table: g_rope[t*64 + i] = (cos, sin) for positions[t], pair i.
// ---------------------------------------------------------------------------
__global__ void rope_table(const int* __restrict__ positions, float2* __restrict__ tab)
{
    int idx = blockIdx.x * blockDim.x + threadIdx.x;   // < TOK*64
    int i = idx & 63;
    int t = idx >> 6;
    float inv = exp2f(-(float)i * (13.287712379549449f / 64.0f));
    float f = (float)positions[t] * inv;
    float sn, cs;
    sincosf(f, &sn, &cs);
    tab[idx] = make_float2(cs, sn);
}

// ---------------------------------------------------------------------------
// GEMM config: CTA 128x128, BK=64, 2-stage cp.async, 128 threads
// (4 warps 2x2, warp tile 64x64 — balanced ldsm:MMA), 3 CTAs/SM.
// R13 mainloop (best known).
// ---------------------------------------------------------------------------
#define BM 128
#define BN 128
#define BK 64
#define PADK 72                        // halves per smem row (64 + 8 pad)
#define TILEA (128 * PADK * 2)         // 18432 B
#define STAGEB (2 * TILEA)             // 36864 B
#define GEMM_SMEM (2 * STAGEB)         // 73728 B (2 stages)

#define GEMM_MAINLOOP64(Aptr, Bptr, Kval)                                        \
    const int NCH = (Kval) >> 6;                                                 \
    auto load_chunk = [&](int cc, int stg) {                                     \
        const uint32_t sb = sbase + stg * STAGEB;                                \
        const int kc = cc * BK;                                                  \
        _Pragma("unroll")                                                        \
        for (int i = 0; i < 8; i++) {                                            \
            int op = tid + i * 128;       /* 0..1023 */                          \
            int row = op >> 3;                                                   \
            int ck = op & 7;                                                     \
            uint32_t soff = (uint32_t)(row * PADK * 2 + ck * 16);                \
            cp16(sb + soff, (Aptr) + (size_t)(m0 + row) * (Kval) + kc + ck * 8); \
            cp16(sb + TILEA + soff,                                              \
                 (Bptr) + (size_t)(n0 + row) * (Kval) + kc + ck * 8);            \
        }                                                                        \
        cp_commit();                                                             \
    };                                                                           \
    load_chunk(0, 0);                                                            \
    const int a_row = (lane & 15);                                               \
    const int a_col = ((lane >> 4) & 1) * 8;                                     \
    const int b_row = (lane & 7) + ((lane & 16) ? 8 : 0);                        \
    const int b_col = ((lane & 8) ? 8 : 0);                                      \
    for (int cch = 0; cch < NCH; cch++) {                                        \
        cp_wait<0>();                                                            \
        __syncthreads();                                                         \
        if (cch + 1 < NCH) load_chunk(cch + 1, (cch + 1) & 1);                   \
        const uint32_t sA = sbase + (cch & 1) * STAGEB;                          \
        const uint32_t sB = sA + TILEA;                                          \
        _Pragma("unroll")                                                        \
        for (int s = 0; s < 4; s++) {                                            \
            uint32_t af[16], bf[8];                                              \
            _Pragma("unroll")                                                    \
            for (int i = 0; i < 4; i++) {                                        \
                int row = wm * 64 + i * 16 + a_row;                              \
                ldsm4(&af[i * 4],                                                \
                      sA + (uint32_t)((row * PADK + s * 16 + a_col) * 2));       \
            }                                                                    \
            _Pragma("unroll")                                                    \
            for (int half = 0; half < 2; half++) {                               \
                _Pragma("unroll")                                                \
                for (int j2 = 0; j2 < 2; j2++) {                                 \
                    int row = wn * 64 + (half * 2 + j2) * 16 + b_row;            \
                    ldsm4(&bf[j2 * 4],                                           \
                          sB + (uint32_t)((row * PADK + s * 16 + b_col) * 2));   \
                }                                                                \
                _Pragma("unroll")                                                \
                for (int i = 0; i < 4; i++)                                      \
                    _Pragma("unroll")                                            \
                    for (int j = 0; j < 4; j++)                                  \
                        mma16816(c[i][half * 4 + j], &af[i * 4], &bf[j * 2]);    \
            }                                                                    \
        }                                                                        \
    }

// ---------------------------------------------------------------------------
// Plain GEMM: C[M,N] = A @ B^T, fp32 out (O-projection).
// ---------------------------------------------------------------------------
__global__ __launch_bounds__(128, 3)
void gemm_f16(const __half* __restrict__ Ah, const __half* __restrict__ Bh,
              float* __restrict__ C, int N, int K)
{
    extern __shared__ char smraw[];
    const uint32_t sbase = smem_u32(smraw);

    const int tid = threadIdx.x;
    const int wid = tid >> 5;
    const int lane = tid & 31;
    const int wm = wid >> 1;          // 0..1 (64 rows)
    const int wn = wid & 1;           // 0..1 (64 cols)
    const int m0 = blockIdx.y * BM;
    const int n0 = blockIdx.x * BN;

    float c[4][8][4];
#pragma unroll
    for (int i = 0; i < 4; i++)
#pragma unroll
        for (int j = 0; j < 8; j++)
#pragma unroll
            for (int q = 0; q < 4; q++) c[i][j][q] = 0.f;

    GEMM_MAINLOOP64(Ah, Bh, K)

    const int g = lane >> 2;
    const int tq = lane & 3;
#pragma unroll
    for (int i = 0; i < 4; i++) {
        int row0 = m0 + wm * 64 + i * 16 + g;
#pragma unroll
        for (int j = 0; j < 8; j++) {
            int col = n0 + wn * 64 + j * 8 + tq * 2;
            float2 v0 = {c[i][j][0], c[i][j][1]};
            float2 v1 = {c[i][j][2], c[i][j][3]};
            *(float2*)&C[(size_t)row0 * N + col] = v0;
            *(float2*)&C[(size_t)(row0 + 8) * N + col] = v1;
        }
    }
}

// ---------------------------------------------------------------------------
// QKV GEMM with fused RoPE (table lookup) + fp16 head-major epilogue.
// ---------------------------------------------------------------------------
#define SCPAD 132   // fp32 row stride in epilogue smem (128*132*4 = 67584 <= 73728)

__global__ __launch_bounds__(128, 3)
void gemm_qkv(const __half* __restrict__ Ah, const __half* __restrict__ Bh,
              const float2* __restrict__ rtab,
              __half* __restrict__ Qh, __half* __restrict__ Kh,
              __half* __restrict__ Vh, int N, int K)
{
    extern __shared__ char smraw[];
    const uint32_t sbase = smem_u32(smraw);

    const int tid = threadIdx.x;
    const int wid = tid >> 5;
    const int lane = tid & 31;
    const int wm = wid >> 1;
    const int wn = wid & 1;
    const int m0 = blockIdx.y * BM;
    const int n0 = blockIdx.x * BN;

    float c[4][8][4];
#pragma unroll
    for (int i = 0; i < 4; i++)
#pragma unroll
        for (int j = 0; j < 8; j++)
#pragma unroll
            for (int q = 0; q < 4; q++) c[i][j][q] = 0.f;

    GEMM_MAINLOOP64(Ah, Bh, K)

    // ---- fused epilogue: stage fp32 tile in smem ----
    __syncthreads();
    float* sc = (float*)smraw;       // [128][SCPAD]

    const int g = lane >> 2;
    const int tq = lane & 3;
#pragma unroll
    for (int i = 0; i < 4; i++) {
        int r0 = wm * 64 + i * 16 + g;
#pragma unroll
        for (int j = 0; j < 8; j++) {
            int col = wn * 64 + j * 8 + tq * 2;
            *(float2*)&sc[r0 * SCPAD + col] = make_float2(c[i][j][0], c[i][j][1]);
            *(float2*)&sc[(r0 + 8) * SCPAD + col] = make_float2(c[i][j][2], c[i][j][3]);
        }
    }
    __syncthreads();

    const int region = n0 >> 12;
    const int h = (n0 & 4095) >> 7;
    const float qscale = (region == 0) ? 0.08838834764831845f : 1.0f;
    __half* outp = (region == 0) ? Qh : (region == 1 ? Kh : Vh);

    // 128 threads: 16 col-threads x 8 row-threads; 16 row iterations
    const int i0 = (tid & 15) * 4;
    const int rbase = tid >> 4;       // 0..7

#pragma unroll 1
    for (int rr = 0; rr < 16; rr++) {
        int row = rbase + rr * 8;
        int t = m0 + row;
        int bb = t >> 11;
        int ss = t & 2047;
        __half* dp = outp + ((size_t)(bb * NH + h) * S_SZ + ss) * HD;

        float r1v[4], r2v[4];
        if (region < 2) {
            const float2* tp = rtab + (size_t)t * 64 + i0;
#pragma unroll
            for (int ii = 0; ii < 4; ii++) {
                int i = i0 + ii;
                float x1 = sc[row * SCPAD + i];
                float x2 = sc[row * SCPAD + i + 64];
                float2 csn = tp[ii];
                r1v[ii] = (x1 * csn.x - x2 * csn.y) * qscale;
                r2v[ii] = (x2 * csn.x + x1 * csn.y) * qscale;
            }
        } else {
#pragma unroll
            for (int ii = 0; ii < 4; ii++) {
                int i = i0 + ii;
                r1v[ii] = sc[row * SCPAD + i];
                r2v[ii] = sc[row * SCPAD + i + 64];
            }
        }
        *(uint32_t*)&dp[i0]     = packh2(r1v[0], r1v[1]);
        *(uint32_t*)&dp[i0 + 2] = packh2(r1v[2], r1v[3]);
        *(uint32_t*)&dp[i0 + 64] = packh2(r2v[0], r2v[1]);
        *(uint32_t*)&dp[i0 + 66] = packh2(r2v[2], r2v[3]);
    }
}

// ---------------------------------------------------------------------------
// HMMA flash attention, causal. Br=128 (8 warps x 16 rows), Bc=128.
// (unchanged — best known)
// ---------------------------------------------------------------------------
#define ATT_PAD 136
#define KVROWB (ATT_PAD * 2)            // 272 bytes
#define KTILE2 (128 * KVROWB)           // 34816
#define ASTG (2 * KTILE2)               // K, V = 69632
#define ATT_SMEM (2 * ASTG)             // 139264

__global__ __launch_bounds__(256, 1)
void flash_attn_hmma(const __half* __restrict__ Qh, const __half* __restrict__ Kh,
                     const __half* __restrict__ Vh, __half* __restrict__ Xh)
{
    extern __shared__ char smraw[];
    const uint32_t sbase = smem_u32(smraw);

    const int tid = threadIdx.x;
    const int wid = tid >> 5;
    const int lane = tid & 31;
    const int g = lane >> 2;
    const int tq = lane & 3;

    const int qb = 15 - (int)blockIdx.x;
    const int bh = blockIdx.y;
    const int b = bh >> 5;
    const int h = bh & 31;
    const size_t hb = (size_t)bh * S_SZ * HD;
    const int row0 = qb * 128;
    const int wr = wid * 16;
    const int nkb = qb + 1;

    uint32_t qhf[8][4];
    {
        const __half* qsrc = Qh + hb + (size_t)row0 * HD;
#pragma unroll
        for (int i = 0; i < 8; i++) {
            int op = tid + i * 256;
            int r = op >> 4;
            int ck = op & 15;
            cp16(sbase + (uint32_t)(r * KVROWB + ck * 16), qsrc + (size_t)r * HD + ck * 8);
        }
        cp_commit();
        cp_wait<0>();
        __syncthreads();
#pragma unroll
        for (int ks = 0; ks < 8; ks++) {
            uint32_t off = (uint32_t)((wr + (lane & 15)) * KVROWB +
                                      (ks * 16 + ((lane >> 4) << 3)) * 2);
            ldsm4(qhf[ks], sbase + off);
        }
        __syncthreads();
    }

    float o[16][4];
#pragma unroll
    for (int j = 0; j < 16; j++)
#pragma unroll
        for (int q = 0; q < 4; q++) o[j][q] = 0.f;
    float m_old0 = -1e30f, m_old1 = -1e30f, l0 = 0.f, l1 = 0.f;

    auto kvload = [&](int kb, int stg) {
        const uint32_t sb = sbase + stg * ASTG;
        const size_t src0 = hb + (size_t)kb * 128 * HD;
#pragma unroll
        for (int i = 0; i < 8; i++) {
            int op = tid + i * 256;
            int r = op >> 4;
            int ck = op & 15;
            uint32_t soff = (uint32_t)(r * KVROWB + ck * 16);
            size_t goff = src0 + (size_t)r * HD + ck * 8;
            cp16(sb + soff, Kh + goff);
            cp16(sb + KTILE2 + soff, Vh + goff);
        }
        cp_commit();
    };

    kvload(0, 0);

    const int r_g = row0 + wr + g;

    for (int kb = 0; kb < nkb; kb++) {
        if (kb + 1 < nkb) kvload(kb + 1, (kb + 1) & 1);
        else cp_commit();
        cp_wait<1>();
        __syncthreads();

        const uint32_t sK = sbase + (kb & 1) * ASTG;
        const uint32_t sV = sK + KTILE2;

        float s[16][4];
#pragma unroll
        for (int j = 0; j < 16; j++)
#pragma unroll
            for (int q = 0; q < 4; q++) s[j][q] = 0.f;

#pragma unroll
        for (int ks = 0; ks < 8; ks++) {
            uint32_t bk[32];
#pragma unroll
            for (int j2 = 0; j2 < 8; j2++) {
                int r = j2 * 16 + (lane & 7) + ((lane & 16) ? 8 : 0);
                uint32_t off = (uint32_t)(r * KVROWB + (ks * 16 + ((lane & 8) ? 8 : 0)) * 2);
                ldsm4(&bk[j2 * 4], sK + off);
            }
#pragma unroll
            for (int j = 0; j < 16; j++) mma16816(s[j], qhf[ks], &bk[j * 2]);
        }

        const int kv0 = kb * 128;
        if (kv0 + 127 > row0 + wr) {
#pragma unroll
            for (int j = 0; j < 16; j++) {
                int cc = kv0 + j * 8 + 2 * tq;
                if (cc > r_g) s[j][0] = -1e30f;
                if (cc + 1 > r_g) s[j][1] = -1e30f;
                if (cc > r_g + 8) s[j][2] = -1e30f;
                if (cc + 1 > r_g + 8) s[j][3] = -1e30f;
            }
        }

        float mx0 = -1e30f, mx1 = -1e30f;
#pragma unroll
        for (int j = 0; j < 16; j++) {
            mx0 = fmaxf(mx0, fmaxf(s[j][0], s[j][1]));
            mx1 = fmaxf(mx1, fmaxf(s[j][2], s[j][3]));
        }
        mx0 = fmaxf(mx0, __shfl_xor_sync(0xffffffffu, mx0, 1));
        mx0 = fmaxf(mx0, __shfl_xor_sync(0xffffffffu, mx0, 2));
        mx1 = fmaxf(mx1, __shfl_xor_sync(0xffffffffu, mx1, 1));
        mx1 = fmaxf(mx1, __shfl_xor_sync(0xffffffffu, mx1, 2));

        float mn0 = fmaxf(m_old0, mx0);
        float mn1 = fmaxf(m_old1, mx1);
        float a0 = __expf(m_old0 - mn0);
        float a1 = __expf(m_old1 - mn1);

        float sum0 = 0.f, sum1 = 0.f;
        uint32_t pa[8][4];
#pragma unroll
        for (int ks = 0; ks < 8; ks++) {
            float p00 = __expf(s[2 * ks][0] - mn0);
            float p01 = __expf(s[2 * ks][1] - mn0);
            float p02 = __expf(s[2 * ks][2] - mn1);
            float p03 = __expf(s[2 * ks][3] - mn1);
            float p10 = __expf(s[2 * ks + 1][0] - mn0);
            float p11 = __expf(s[2 * ks + 1][1] - mn0);
            float p12 = __expf(s[2 * ks + 1][2] - mn1);
            float p13 = __expf(s[2 * ks + 1][3] - mn1);
            sum0 += p00 + p01 + p10 + p11;
            sum1 += p02 + p03 + p12 + p13;
            pa[ks][0] = packh2(p00, p01);
            pa[ks][1] = packh2(p02, p03);
            pa[ks][2] = packh2(p10, p11);
            pa[ks][3] = packh2(p12, p13);
        }
        sum0 += __shfl_xor_sync(0xffffffffu, sum0, 1);
        sum0 += __shfl_xor_sync(0xffffffffu, sum0, 2);
        sum1 += __shfl_xor_sync(0xffffffffu, sum1, 1);
        sum1 += __shfl_xor_sync(0xffffffffu, sum1, 2);

        l0 = l0 * a0 + sum0;
        l1 = l1 * a1 + sum1;
        m_old0 = mn0;
        m_old1 = mn1;

#pragma unroll
        for (int j = 0; j < 16; j++) {
            o[j][0] *= a0; o[j][1] *= a0;
            o[j][2] *= a1; o[j][3] *= a1;
        }

#pragma unroll
        for (int ks = 0; ks < 8; ks++) {
#pragma unroll
            for (int jj = 0; jj < 8; jj++) {
                int krow = ks * 16 + (lane & 15);
                uint32_t off = (uint32_t)(krow * KVROWB + (jj * 16 + ((lane & 16) ? 8 : 0)) * 2);
                uint32_t bv[4];
                ldsm4t(bv, sV + off);
                mma16816(o[jj * 2], pa[ks], &bv[0]);
                mma16816(o[jj * 2 + 1], pa[ks], &bv[2]);
            }
        }
        __syncthreads();
    }

    const float il0 = 1.f / l0;
    const float il1 = 1.f / l1;
    const int tok0 = b * S_SZ + row0 + wr;
#pragma unroll
    for (int j = 0; j < 16; j++) {
        int col = h * HD + j * 8 + 2 * tq;
        size_t i0 = (size_t)(tok0 + g) * HID + col;
        size_t i1 = (size_t)(tok0 + g + 8) * HID + col;
        *(uint32_t*)&Xh[i0] = packh2(o[j][0] * il0, o[j][1] * il0);
        *(uint32_t*)&Xh[i1] = packh2(o[j][2] * il1, o[j][3] * il1);
    }
}

// ---------------------------------------------------------------------------
// Launch
// ---------------------------------------------------------------------------
extern "C" void kernel_launch(void* const* d_in, const int* in_sizes, int n_in,
                              void* d_out, int out_size)
{
    const float* hidden = (const float*)d_in[0];
    const int* positions = (const int*)d_in[1];
    const float* W_pack = (const float*)d_in[2];
    const float* W_o = (const float*)d_in[3];
    float* out = (float*)d_out;

    void* v_ah; cudaGetSymbolAddress(&v_ah, g_Ah);
    void* v_wp; cudaGetSymbolAddress(&v_wp, g_Wp);
    void* v_wo; cudaGetSymbolAddress(&v_wo, g_Wo);
    void* v_xh; cudaGetSymbolAddress(&v_xh, g_Xh);
    void* v_qh; cudaGetSymbolAddress(&v_qh, g_Qh);
    void* v_kh; cudaGetSymbolAddress(&v_kh, g_Kh);
    void* v_vh; cudaGetSymbolAddress(&v_vh, g_Vh);
    void* v_rt; cudaGetSymbolAddress(&v_rt, g_rope);

    cudaFuncSetAttribute(gemm_f16, cudaFuncAttributeMaxDynamicSharedMemorySize, GEMM_SMEM);
    cudaFuncSetAttribute(gemm_qkv, cudaFuncAttributeMaxDynamicSharedMemorySize, GEMM_SMEM);
    cudaFuncSetAttribute(flash_attn_hmma, cudaFuncAttributeMaxDynamicSharedMemorySize, ATT_SMEM);

    // 0) operand prep + RoPE table
    {
        int n8 = TOK * HID / 8;
        conv_f16<<<(n8 + 255) / 256, 256>>>(hidden, (__half*)v_ah, n8);
        int w8 = PROJ3 * HID / 8;
        conv_f16<<<(w8 + 255) / 256, 256>>>(W_pack, (__half*)v_wp, w8);
        int o8 = HID * HID / 8;
        conv_f16<<<(o8 + 255) / 256, 256>>>(W_o, (__half*)v_wo, o8);
        rope_table<<<TOK * 64 / 256, 256>>>(positions, (float2*)v_rt);
    }

    // 1) QKV projection + fused RoPE + fp16 head-major conversion
    {
        dim3 grid(PROJ3 / BN, TOK / BM);  // 96 x 32
        gemm_qkv<<<grid, 128, GEMM_SMEM>>>((const __half*)v_ah, (const __half*)v_wp,
                                           (const float2*)v_rt,
                                           (__half*)v_qh, (__half*)v_kh, (__half*)v_vh,
                                           PROJ3, HID);
    }

    // 2) Causal attention on tensor cores; writes Xh directly
    {
        dim3 grid(S_SZ / 128, B_SZ * NH);  // 16 x 64
        flash_attn_hmma<<<grid, 256, ATT_SMEM>>>((const __half*)v_qh, (const __half*)v_kh,
                                                 (const __half*)v_vh, (__half*)v_xh);
    }

    // 3) out = attn @ W_o^T
    {
        dim3 grid(HID / BN, TOK / BM);  // 32 x 32
        gemm_f16<<<grid, 128, GEMM_SMEM>>>((const __half*)v_xh, (const __half*)v_wo,
                                           out, HID, HID);
    }
}

// round 16
// speedup vs baseline: 1.0293x; 1.0024x over previous
#include <cuda_runtime.h>
#include <cuda_fp16.h>
#include <math.h>
#include <stdint.h>

// Problem constants
#define B_SZ 2
#define S_SZ 2048
#define HID 4096
#define NH 32
#define HD 128
#define TOK (B_SZ * S_SZ)          // 4096 tokens
#define PROJ3 (3 * HID)            // 12288

// Scratch (static device globals — allocation-free rule)
__device__ __half g_Ah[(size_t)TOK * HID];
__device__ __half g_Wp[(size_t)PROJ3 * HID];
__device__ __half g_Wo[(size_t)HID * HID];
__device__ __half g_Xh[(size_t)TOK * HID];
// head-major fp16 attention operands [b*NH+h][s][d]
__device__ __half g_Qh[(size_t)TOK * HID];
__device__ __half g_Kh[(size_t)TOK * HID];
__device__ __half g_Vh[(size_t)TOK * HID];
// RoPE cos/sin table per (token, pair-index)
__device__ float2 g_rope[(size_t)TOK * 64];

// ---------------------------------------------------------------------------
// Inline PTX helpers
// ---------------------------------------------------------------------------
__device__ __forceinline__ uint32_t smem_u32(const void* p) {
    uint32_t a;
    asm("{ .reg .u64 t; cvta.to.shared.u64 t, %1; cvt.u32.u64 %0, t; }" : "=r"(a) : "l"(p));
    return a;
}
__device__ __forceinline__ void cp16(uint32_t dst, const void* src) {
    asm volatile("cp.async.cg.shared.global [%0], [%1], 16;" :: "r"(dst), "l"(src) : "memory");
}
__device__ __forceinline__ void cp_commit() { asm volatile("cp.async.commit_group;" ::: "memory"); }
template <int N>
__device__ __forceinline__ void cp_wait() {
    asm volatile("cp.async.wait_group %0;" :: "n"(N) : "memory");
}
__device__ __forceinline__ void ldsm4(uint32_t r[4], uint32_t addr) {
    asm volatile("ldmatrix.sync.aligned.m8n8.x4.shared.b16 {%0,%1,%2,%3}, [%4];"
                 : "=r"(r[0]), "=r"(r[1]), "=r"(r[2]), "=r"(r[3]) : "r"(addr));
}
__device__ __forceinline__ void ldsm4t(uint32_t r[4], uint32_t addr) {
    asm volatile("ldmatrix.sync.aligned.m8n8.x4.trans.shared.b16 {%0,%1,%2,%3}, [%4];"
                 : "=r"(r[0]), "=r"(r[1]), "=r"(r[2]), "=r"(r[3]) : "r"(addr));
}
__device__ __forceinline__ void mma16816(float c[4], const uint32_t a[4], const uint32_t b[2]) {
    asm volatile(
        "mma.sync.aligned.m16n8k16.row.col.f32.f16.f16.f32 "
        "{%0,%1,%2,%3}, {%4,%5,%6,%7}, {%8,%9}, {%0,%1,%2,%3};"
        : "+f"(c[0]), "+f"(c[1]), "+f"(c[2]), "+f"(c[3])
        : "r"(a[0]), "r"(a[1]), "r"(a[2]), "r"(a[3]), "r"(b[0]), "r"(b[1]));
}
__device__ __forceinline__ uint32_t packh2(float a, float b) {
    __half2 h = __floats2half2_rn(a, b);
    return *(uint32_t*)&h;
}

// ---------------------------------------------------------------------------
// fp32 -> fp16 round. 8 elements/thread.
// ---------------------------------------------------------------------------
__global__ void conv_f16(const float* __restrict__ x, __half* __restrict__ y, int n8)
{
    int i = blockIdx.x * blockDim.x + threadIdx.x;
    if (i >= n8) return;
    const float4* xp = (const float4*)x + (size_t)i * 2;
    float4 a = xp[0], b = xp[1];
    float v[8] = {a.x, a.y, a.z, a.w, b.x, b.y, b.z, b.w};
    __half h[8];
#pragma unroll
    for (int j = 0; j < 8; j++) h[j] = __float2half_rn(v[j]);
    *((uint4*)y + i) = *(const uint4*)h;
}

// ---------------------------------------------------------------------------
// Build RoPE table: g_rope[t*64 + i] = (cos, sin) for positions[t], pair i.
// ---------------------------------------------------------------------------
__global__ void rope_table(const int* __restrict__ positions, float2* __restrict__ tab)
{
    int idx = blockIdx.x * blockDim.x + threadIdx.x;   // < TOK*64
    int i = idx & 63;
    int t = idx >> 6;
    float inv = exp2f(-(float)i * (13.287712379549449f / 64.0f));
    float f = (float)positions[t] * inv;
    float sn, cs;
    sincosf(f, &sn, &cs);
    tab[idx] = make_float2(cs, sn);
}

// ---------------------------------------------------------------------------
// GEMM config: CTA 128x128, BK=64, 2-stage cp.async, 128 threads
// (4 warps 2x2, warp tile 64x64 — balanced ldsm:MMA), 3 CTAs/SM.
// R13 mainloop (best known).
// ---------------------------------------------------------------------------
#define BM 128
#define BN 128
#define BK 64
#define PADK 72                        // halves per smem row (64 + 8 pad)
#define TILEA (128 * PADK * 2)         // 18432 B
#define STAGEB (2 * TILEA)             // 36864 B
#define GEMM_SMEM (2 * STAGEB)         // 73728 B (2 stages)

#define GEMM_MAINLOOP64(Aptr, Bptr, Kval)                                        \
    const int NCH = (Kval) >> 6;                                                 \
    auto load_chunk = [&](int cc, int stg) {                                     \
        const uint32_t sb = sbase + stg * STAGEB;                                \
        const int kc = cc * BK;                                                  \
        _Pragma("unroll")                                                        \
        for (int i = 0; i < 8; i++) {                                            \
            int op = tid + i * 128;       /* 0..1023 */                          \
            int row = op >> 3;                                                   \
            int ck = op & 7;                                                     \
            uint32_t soff = (uint32_t)(row * PADK * 2 + ck * 16);                \
            cp16(sb + soff, (Aptr) + (size_t)(m0 + row) * (Kval) + kc + ck * 8); \
            cp16(sb + TILEA + soff,                                              \
                 (Bptr) + (size_t)(n0 + row) * (Kval) + kc + ck * 8);            \
        }                                                                        \
        cp_commit();                                                             \
    };                                                                           \
    load_chunk(0, 0);                                                            \
    const int a_row = (lane & 15);                                               \
    const int a_col = ((lane >> 4) & 1) * 8;                                     \
    const int b_row = (lane & 7) + ((lane & 16) ? 8 : 0);                        \
    const int b_col = ((lane & 8) ? 8 : 0);                                      \
    for (int cch = 0; cch < NCH; cch++) {                                        \
        cp_wait<0>();                                                            \
        __syncthreads();                                                         \
        if (cch + 1 < NCH) load_chunk(cch + 1, (cch + 1) & 1);                   \
        const uint32_t sA = sbase + (cch & 1) * STAGEB;                          \
        const uint32_t sB = sA + TILEA;                                          \
        _Pragma("unroll")                                                        \
        for (int s = 0; s < 4; s++) {                                            \
            uint32_t af[16], bf[8];                                              \
            _Pragma("unroll")                                                    \
            for (int i = 0; i < 4; i++) {                                        \
                int row = wm * 64 + i * 16 + a_row;                              \
                ldsm4(&af[i * 4],                                                \
                      sA + (uint32_t)((row * PADK + s * 16 + a_col) * 2));       \
            }                                                                    \
            _Pragma("unroll")                                                    \
            for (int half = 0; half < 2; half++) {                               \
                _Pragma("unroll")                                                \
                for (int j2 = 0; j2 < 2; j2++) {                                 \
                    int row = wn * 64 + (half * 2 + j2) * 16 + b_row;            \
                    ldsm4(&bf[j2 * 4],                                           \
                          sB + (uint32_t)((row * PADK + s * 16 + b_col) * 2));   \
                }                                                                \
                _Pragma("unroll")                                                \
                for (int i = 0; i < 4; i++)                                      \
                    _Pragma("unroll")                                            \
                    for (int j = 0; j < 4; j++)                                  \
                        mma16816(c[i][half * 4 + j], &af[i * 4], &bf[j * 2]);    \
            }                                                                    \
        }                                                                        \
    }

// ---------------------------------------------------------------------------
// Plain GEMM: C[M,N] = A @ B^T, fp32 out (O-projection).
// ---------------------------------------------------------------------------
__global__ __launch_bounds__(128, 3)
void gemm_f16(const __half* __restrict__ Ah, const __half* __restrict__ Bh,
              float* __restrict__ C, int N, int K)
{
    extern __shared__ char smraw[];
    const uint32_t sbase = smem_u32(smraw);

    const int tid = threadIdx.x;
    const int wid = tid >> 5;
    const int lane = tid & 31;
    const int wm = wid >> 1;          // 0..1 (64 rows)
    const int wn = wid & 1;           // 0..1 (64 cols)
    const int m0 = blockIdx.y * BM;
    const int n0 = blockIdx.x * BN;

    float c[4][8][4];
#pragma unroll
    for (int i = 0; i < 4; i++)
#pragma unroll
        for (int j = 0; j < 8; j++)
#pragma unroll
            for (int q = 0; q < 4; q++) c[i][j][q] = 0.f;

    GEMM_MAINLOOP64(Ah, Bh, K)

    const int g = lane >> 2;
    const int tq = lane & 3;
#pragma unroll
    for (int i = 0; i < 4; i++) {
        int row0 = m0 + wm * 64 + i * 16 + g;
#pragma unroll
        for (int j = 0; j < 8; j++) {
            int col = n0 + wn * 64 + j * 8 + tq * 2;
            float2 v0 = {c[i][j][0], c[i][j][1]};
            float2 v1 = {c[i][j][2], c[i][j][3]};
            *(float2*)&C[(size_t)row0 * N + col] = v0;
            *(float2*)&C[(size_t)(row0 + 8) * N + col] = v1;
        }
    }
}

// ---------------------------------------------------------------------------
// QKV GEMM with fused RoPE (table lookup) + fp16 head-major epilogue.
// ---------------------------------------------------------------------------
#define SCPAD 132   // fp32 row stride in epilogue smem (128*132*4 = 67584 <= 73728)

__global__ __launch_bounds__(128, 3)
void gemm_qkv(const __half* __restrict__ Ah, const __half* __restrict__ Bh,
              const float2* __restrict__ rtab,
              __half* __restrict__ Qh, __half* __restrict__ Kh,
              __half* __restrict__ Vh, int N, int K)
{
    extern __shared__ char smraw[];
    const uint32_t sbase = smem_u32(smraw);

    const int tid = threadIdx.x;
    const int wid = tid >> 5;
    const int lane = tid & 31;
    const int wm = wid >> 1;
    const int wn = wid & 1;
    const int m0 = blockIdx.y * BM;
    const int n0 = blockIdx.x * BN;

    float c[4][8][4];
#pragma unroll
    for (int i = 0; i < 4; i++)
#pragma unroll
        for (int j = 0; j < 8; j++)
#pragma unroll
            for (int q = 0; q < 4; q++) c[i][j][q] = 0.f;

    GEMM_MAINLOOP64(Ah, Bh, K)

    // ---- fused epilogue: stage fp32 tile in smem ----
    __syncthreads();
    float* sc = (float*)smraw;       // [128][SCPAD]

    const int g = lane >> 2;
    const int tq = lane & 3;
#pragma unroll
    for (int i = 0; i < 4; i++) {
        int r0 = wm * 64 + i * 16 + g;
#pragma unroll
        for (int j = 0; j < 8; j++) {
            int col = wn * 64 + j * 8 + tq * 2;
            *(float2*)&sc[r0 * SCPAD + col] = make_float2(c[i][j][0], c[i][j][1]);
            *(float2*)&sc[(r0 + 8) * SCPAD + col] = make_float2(c[i][j][2], c[i][j][3]);
        }
    }
    __syncthreads();

    const int region = n0 >> 12;
    const int h = (n0 & 4095) >> 7;
    const float qscale = (region == 0) ? 0.08838834764831845f : 1.0f;
    __half* outp = (region == 0) ? Qh : (region == 1 ? Kh : Vh);

    // 128 threads: 16 col-threads x 8 row-threads; 16 row iterations
    const int i0 = (tid & 15) * 4;
    const int rbase = tid >> 4;       // 0..7

#pragma unroll 1
    for (int rr = 0; rr < 16; rr++) {
        int row = rbase + rr * 8;
        int t = m0 + row;
        int bb = t >> 11;
        int ss = t & 2047;
        __half* dp = outp + ((size_t)(bb * NH + h) * S_SZ + ss) * HD;

        float r1v[4], r2v[4];
        if (region < 2) {
            const float2* tp = rtab + (size_t)t * 64 + i0;
#pragma unroll
            for (int ii = 0; ii < 4; ii++) {
                int i = i0 + ii;
                float x1 = sc[row * SCPAD + i];
                float x2 = sc[row * SCPAD + i + 64];
                float2 csn = tp[ii];
                r1v[ii] = (x1 * csn.x - x2 * csn.y) * qscale;
                r2v[ii] = (x2 * csn.x + x1 * csn.y) * qscale;
            }
        } else {
#pragma unroll
            for (int ii = 0; ii < 4; ii++) {
                int i = i0 + ii;
                r1v[ii] = sc[row * SCPAD + i];
                r2v[ii] = sc[row * SCPAD + i + 64];
            }
        }
        *(uint32_t*)&dp[i0]     = packh2(r1v[0], r1v[1]);
        *(uint32_t*)&dp[i0 + 2] = packh2(r1v[2], r1v[3]);
        *(uint32_t*)&dp[i0 + 64] = packh2(r2v[0], r2v[1]);
        *(uint32_t*)&dp[i0 + 66] = packh2(r2v[2], r2v[3]);
    }
}

// ---------------------------------------------------------------------------
// HMMA flash attention, causal. Br=128 (8 warps x 16 rows), Bc=128.
// (unchanged — best known)
// ---------------------------------------------------------------------------
#define ATT_PAD 136
#define KVROWB (ATT_PAD * 2)            // 272 bytes
#define KTILE2 (128 * KVROWB)           // 34816
#define ASTG (2 * KTILE2)               // K, V = 69632
#define ATT_SMEM (2 * ASTG)             // 139264

__global__ __launch_bounds__(256, 1)
void flash_attn_hmma(const __half* __restrict__ Qh, const __half* __restrict__ Kh,
                     const __half* __restrict__ Vh, __half* __restrict__ Xh)
{
    extern __shared__ char smraw[];
    const uint32_t sbase = smem_u32(smraw);

    const int tid = threadIdx.x;
    const int wid = tid >> 5;
    const int lane = tid & 31;
    const int g = lane >> 2;
    const int tq = lane & 3;

    const int qb = 15 - (int)blockIdx.x;
    const int bh = blockIdx.y;
    const int b = bh >> 5;
    const int h = bh & 31;
    const size_t hb = (size_t)bh * S_SZ * HD;
    const int row0 = qb * 128;
    const int wr = wid * 16;
    const int nkb = qb + 1;

    uint32_t qhf[8][4];
    {
        const __half* qsrc = Qh + hb + (size_t)row0 * HD;
#pragma unroll
        for (int i = 0; i < 8; i++) {
            int op = tid + i * 256;
            int r = op >> 4;
            int ck = op & 15;
            cp16(sbase + (uint32_t)(r * KVROWB + ck * 16), qsrc + (size_t)r * HD + ck * 8);
        }
        cp_commit();
        cp_wait<0>();
        __syncthreads();
#pragma unroll
        for (int ks = 0; ks < 8; ks++) {
            uint32_t off = (uint32_t)((wr + (lane & 15)) * KVROWB +
                                      (ks * 16 + ((lane >> 4) << 3)) * 2);
            ldsm4(qhf[ks], sbase + off);
        }
        __syncthreads();
    }

    float o[16][4];
#pragma unroll
    for (int j = 0; j < 16; j++)
#pragma unroll
        for (int q = 0; q < 4; q++) o[j][q] = 0.f;
    float m_old0 = -1e30f, m_old1 = -1e30f, l0 = 0.f, l1 = 0.f;

    auto kvload = [&](int kb, int stg) {
        const uint32_t sb = sbase + stg * ASTG;
        const size_t src0 = hb + (size_t)kb * 128 * HD;
#pragma unroll
        for (int i = 0; i < 8; i++) {
            int op = tid + i * 256;
            int r = op >> 4;
            int ck = op & 15;
            uint32_t soff = (uint32_t)(r * KVROWB + ck * 16);
            size_t goff = src0 + (size_t)r * HD + ck * 8;
            cp16(sb + soff, Kh + goff);
            cp16(sb + KTILE2 + soff, Vh + goff);
        }
        cp_commit();
    };

    kvload(0, 0);

    const int r_g = row0 + wr + g;

    for (int kb = 0; kb < nkb; kb++) {
        if (kb + 1 < nkb) kvload(kb + 1, (kb + 1) & 1);
        else cp_commit();
        cp_wait<1>();
        __syncthreads();

        const uint32_t sK = sbase + (kb & 1) * ASTG;
        const uint32_t sV = sK + KTILE2;

        float s[16][4];
#pragma unroll
        for (int j = 0; j < 16; j++)
#pragma unroll
            for (int q = 0; q < 4; q++) s[j][q] = 0.f;

#pragma unroll
        for (int ks = 0; ks < 8; ks++) {
            uint32_t bk[32];
#pragma unroll
            for (int j2 = 0; j2 < 8; j2++) {
                int r = j2 * 16 + (lane & 7) + ((lane & 16) ? 8 : 0);
                uint32_t off = (uint32_t)(r * KVROWB + (ks * 16 + ((lane & 8) ? 8 : 0)) * 2);
                ldsm4(&bk[j2 * 4], sK + off);
            }
#pragma unroll
            for (int j = 0; j < 16; j++) mma16816(s[j], qhf[ks], &bk[j * 2]);
        }

        const int kv0 = kb * 128;
        if (kv0 + 127 > row0 + wr) {
#pragma unroll
            for (int j = 0; j < 16; j++) {
                int cc = kv0 + j * 8 + 2 * tq;
                if (cc > r_g) s[j][0] = -1e30f;
                if (cc + 1 > r_g) s[j][1] = -1e30f;
                if (cc > r_g + 8) s[j][2] = -1e30f;
                if (cc + 1 > r_g + 8) s[j][3] = -1e30f;
            }
        }

        float mx0 = -1e30f, mx1 = -1e30f;
#pragma unroll
        for (int j = 0; j < 16; j++) {
            mx0 = fmaxf(mx0, fmaxf(s[j][0], s[j][1]));
            mx1 = fmaxf(mx1, fmaxf(s[j][2], s[j][3]));
        }
        mx0 = fmaxf(mx0, __shfl_xor_sync(0xffffffffu, mx0, 1));
        mx0 = fmaxf(mx0, __shfl_xor_sync(0xffffffffu, mx0, 2));
        mx1 = fmaxf(mx1, __shfl_xor_sync(0xffffffffu, mx1, 1));
        mx1 = fmaxf(mx1, __shfl_xor_sync(0xffffffffu, mx1, 2));

        float mn0 = fmaxf(m_old0, mx0);
        float mn1 = fmaxf(m_old1, mx1);
        float a0 = __expf(m_old0 - mn0);
        float a1 = __expf(m_old1 - mn1);

        float sum0 = 0.f, sum1 = 0.f;
        uint32_t pa[8][4];
#pragma unroll
        for (int ks = 0; ks < 8; ks++) {
            float p00 = __expf(s[2 * ks][0] - mn0);
            float p01 = __expf(s[2 * ks][1] - mn0);
            float p02 = __expf(s[2 * ks][2] - mn1);
            float p03 = __expf(s[2 * ks][3] - mn1);
            float p10 = __expf(s[2 * ks + 1][0] - mn0);
            float p11 = __expf(s[2 * ks + 1][1] - mn0);
            float p12 = __expf(s[2 * ks + 1][2] - mn1);
            float p13 = __expf(s[2 * ks + 1][3] - mn1);
            sum0 += p00 + p01 + p10 + p11;
            sum1 += p02 + p03 + p12 + p13;
            pa[ks][0] = packh2(p00, p01);
            pa[ks][1] = packh2(p02, p03);
            pa[ks][2] = packh2(p10, p11);
            pa[ks][3] = packh2(p12, p13);
        }
        sum0 += __shfl_xor_sync(0xffffffffu, sum0, 1);
        sum0 += __shfl_xor_sync(0xffffffffu, sum0, 2);
        sum1 += __shfl_xor_sync(0xffffffffu, sum1, 1);
        sum1 += __shfl_xor_sync(0xffffffffu, sum1, 2);

        l0 = l0 * a0 + sum0;
        l1 = l1 * a1 + sum1;
        m_old0 = mn0;
        m_old1 = mn1;

#pragma unroll
        for (int j = 0; j < 16; j++) {
            o[j][0] *= a0; o[j][1] *= a0;
            o[j][2] *= a1; o[j][3] *= a1;
        }

#pragma unroll
        for (int ks = 0; ks < 8; ks++) {
#pragma unroll
            for (int jj = 0; jj < 8; jj++) {
                int krow = ks * 16 + (lane & 15);
                uint32_t off = (uint32_t)(krow * KVROWB + (jj * 16 + ((lane & 16) ? 8 : 0)) * 2);
                uint32_t bv[4];
                ldsm4t(bv, sV + off);
                mma16816(o[jj * 2], pa[ks], &bv[0]);
                mma16816(o[jj * 2 + 1], pa[ks], &bv[2]);
            }
        }
        __syncthreads();
    }

    const float il0 = 1.f / l0;
    const float il1 = 1.f / l1;
    const int tok0 = b * S_SZ + row0 + wr;
#pragma unroll
    for (int j = 0; j < 16; j++) {
        int col = h * HD + j * 8 + 2 * tq;
        size_t i0 = (size_t)(tok0 + g) * HID + col;
        size_t i1 = (size_t)(tok0 + g + 8) * HID + col;
        *(uint32_t*)&Xh[i0] = packh2(o[j][0] * il0, o[j][1] * il0);
        *(uint32_t*)&Xh[i1] = packh2(o[j][2] * il1, o[j][3] * il1);
    }
}

// ---------------------------------------------------------------------------
// Launch — with a captured stream fork: W_o conversion overlaps QKV+attention.
// ---------------------------------------------------------------------------
extern "C" void kernel_launch(void* const* d_in, const int* in_sizes, int n_in,
                              void* d_out, int out_size)
{
    const float* hidden = (const float*)d_in[0];
    const int* positions = (const int*)d_in[1];
    const float* W_pack = (const float*)d_in[2];
    const float* W_o = (const float*)d_in[3];
    float* out = (float*)d_out;

    void* v_ah; cudaGetSymbolAddress(&v_ah, g_Ah);
    void* v_wp; cudaGetSymbolAddress(&v_wp, g_Wp);
    void* v_wo; cudaGetSymbolAddress(&v_wo, g_Wo);
    void* v_xh; cudaGetSymbolAddress(&v_xh, g_Xh);
    void* v_qh; cudaGetSymbolAddress(&v_qh, g_Qh);
    void* v_kh; cudaGetSymbolAddress(&v_kh, g_Kh);
    void* v_vh; cudaGetSymbolAddress(&v_vh, g_Vh);
    void* v_rt; cudaGetSymbolAddress(&v_rt, g_rope);

    cudaFuncSetAttribute(gemm_f16, cudaFuncAttributeMaxDynamicSharedMemorySize, GEMM_SMEM);
    cudaFuncSetAttribute(gemm_qkv, cudaFuncAttributeMaxDynamicSharedMemorySize, GEMM_SMEM);
    cudaFuncSetAttribute(flash_attn_hmma, cudaFuncAttributeMaxDynamicSharedMemorySize, ATT_SMEM);

    // Side stream for W_o conversion (fork/join inside graph capture).
    // Host-side objects only; kernel_launch runs once for correctness and
    // once for capture, so creation count is bounded.
    cudaStream_t s2;
    cudaEvent_t evFork, evJoin;
    cudaStreamCreateWithFlags(&s2, cudaStreamNonBlocking);
    cudaEventCreateWithFlags(&evFork, cudaEventDisableTiming);
    cudaEventCreateWithFlags(&evJoin, cudaEventDisableTiming);

    // Fork: side stream converts W_o (needed only by the final GEMM).
    cudaEventRecord(evFork, 0);
    cudaStreamWaitEvent(s2, evFork, 0);
    {
        int o8 = HID * HID / 8;
        conv_f16<<<(o8 + 255) / 256, 256, 0, s2>>>(W_o, (__half*)v_wo, o8);
    }
    cudaEventRecord(evJoin, s2);

    // Main stream: prep for QKV GEMM
    {
        int n8 = TOK * HID / 8;
        conv_f16<<<(n8 + 255) / 256, 256>>>(hidden, (__half*)v_ah, n8);
        int w8 = PROJ3 * HID / 8;
        conv_f16<<<(w8 + 255) / 256, 256>>>(W_pack, (__half*)v_wp, w8);
        rope_table<<<TOK * 64 / 256, 256>>>(positions, (float2*)v_rt);
    }

    // 1) QKV projection + fused RoPE + fp16 head-major conversion
    {
        dim3 grid(PROJ3 / BN, TOK / BM);  // 96 x 32
        gemm_qkv<<<grid, 128, GEMM_SMEM>>>((const __half*)v_ah, (const __half*)v_wp,
                                           (const float2*)v_rt,
                                           (__half*)v_qh, (__half*)v_kh, (__half*)v_vh,
                                           PROJ3, HID);
    }

    // 2) Causal attention on tensor cores; writes Xh directly
    {
        dim3 grid(S_SZ / 128, B_SZ * NH);  // 16 x 64
        flash_attn_hmma<<<grid, 256, ATT_SMEM>>>((const __half*)v_qh, (const __half*)v_kh,
                                                 (const __half*)v_vh, (__half*)v_xh);
    }

    // Join: O-proj needs W_o conversion done.
    cudaStreamWaitEvent(0, evJoin, 0);

    // 3) out = attn @ W_o^T
    {
        dim3 grid(HID / BN, TOK / BM);  // 32 x 32
        gemm_f16<<<grid, 128, GEMM_SMEM>>>((const __half*)v_xh, (const __half*)v_wo,
                                           out, HID, HID);
    }

    cudaStreamDestroy(s2);
    cudaEventDestroy(evFork);
    cudaEventDestroy(evJoin);
}

// round 17
// speedup vs baseline: 1.0488x; 1.0190x over previous
#include <cuda_runtime.h>
#include <cuda_fp16.h>
#include <math.h>
#include <stdint.h>

// Problem constants
#define B_SZ 2
#define S_SZ 2048
#define HID 4096
#define NH 32
#define HD 128
#define TOK (B_SZ * S_SZ)          // 4096 tokens
#define PROJ3 (3 * HID)            // 12288

// Scratch (static device globals — allocation-free rule)
__device__ __half g_Ah[(size_t)TOK * HID];
__device__ __half g_Wp[(size_t)PROJ3 * HID];
__device__ __half g_Wo[(size_t)HID * HID];
__device__ __half g_Xh[(size_t)TOK * HID];
// head-major fp16 attention operands [b*NH+h][s][d]
__device__ __half g_Qh[(size_t)TOK * HID];
__device__ __half g_Kh[(size_t)TOK * HID];
__device__ __half g_Vh[(size_t)TOK * HID];
// RoPE cos/sin table per (token, pair-index)
__device__ float2 g_rope[(size_t)TOK * 64];

// ---------------------------------------------------------------------------
// Inline PTX helpers
// ---------------------------------------------------------------------------
__device__ __forceinline__ uint32_t smem_u32(const void* p) {
    uint32_t a;
    asm("{ .reg .u64 t; cvta.to.shared.u64 t, %1; cvt.u32.u64 %0, t; }" : "=r"(a) : "l"(p));
    return a;
}
__device__ __forceinline__ void cp16(uint32_t dst, const void* src) {
    asm volatile("cp.async.cg.shared.global [%0], [%1], 16;" :: "r"(dst), "l"(src) : "memory");
}
__device__ __forceinline__ void cp_commit() { asm volatile("cp.async.commit_group;" ::: "memory"); }
template <int N>
__device__ __forceinline__ void cp_wait() {
    asm volatile("cp.async.wait_group %0;" :: "n"(N) : "memory");
}
__device__ __forceinline__ void ldsm4(uint32_t r[4], uint32_t addr) {
    asm volatile("ldmatrix.sync.aligned.m8n8.x4.shared.b16 {%0,%1,%2,%3}, [%4];"
                 : "=r"(r[0]), "=r"(r[1]), "=r"(r[2]), "=r"(r[3]) : "r"(addr));
}
__device__ __forceinline__ void ldsm4t(uint32_t r[4], uint32_t addr) {
    asm volatile("ldmatrix.sync.aligned.m8n8.x4.trans.shared.b16 {%0,%1,%2,%3}, [%4];"
                 : "=r"(r[0]), "=r"(r[1]), "=r"(r[2]), "=r"(r[3]) : "r"(addr));
}
__device__ __forceinline__ void mma16816(float c[4], const uint32_t a[4], const uint32_t b[2]) {
    asm volatile(
        "mma.sync.aligned.m16n8k16.row.col.f32.f16.f16.f32 "
        "{%0,%1,%2,%3}, {%4,%5,%6,%7}, {%8,%9}, {%0,%1,%2,%3};"
        : "+f"(c[0]), "+f"(c[1]), "+f"(c[2]), "+f"(c[3])
        : "r"(a[0]), "r"(a[1]), "r"(a[2]), "r"(a[3]), "r"(b[0]), "r"(b[1]));
}
__device__ __forceinline__ uint32_t packh2(float a, float b) {
    __half2 h = __floats2half2_rn(a, b);
    return *(uint32_t*)&h;
}

// ---------------------------------------------------------------------------
// fp32 -> fp16 round. 8 elements/thread.
// ---------------------------------------------------------------------------
__global__ void conv_f16(const float* __restrict__ x, __half* __restrict__ y, int n8)
{
    int i = blockIdx.x * blockDim.x + threadIdx.x;
    if (i >= n8) return;
    const float4* xp = (const float4*)x + (size_t)i * 2;
    float4 a = xp[0], b = xp[1];
    float v[8] = {a.x, a.y, a.z, a.w, b.x, b.y, b.z, b.w};
    __half h[8];
#pragma unroll
    for (int j = 0; j < 8; j++) h[j] = __float2half_rn(v[j]);
    *((uint4*)y + i) = *(const uint4*)h;
}

// ---------------------------------------------------------------------------
// Build RoPE table: g_rope[t*64 + i] = (cos, sin) for positions[t], pair i.
// ---------------------------------------------------------------------------
__global__ void rope_table(const int* __restrict__ positions, float2* __restrict__ tab)
{
    int idx = blockIdx.x * blockDim.x + threadIdx.x;   // < TOK*64
    int i = idx & 63;
    int t = idx >> 6;
    float inv = exp2f(-(float)i * (13.287712379549449f / 64.0f));
    float f = (float)positions[t] * inv;
    float sn, cs;
    sincosf(f, &sn, &cs);
    tab[idx] = make_float2(cs, sn);
}

// ---------------------------------------------------------------------------
// GEMM config: CTA 128x128, BK=64, 2-stage cp.async, 128 threads
// (4 warps 2x2, warp tile 64x64 — balanced ldsm:MMA), 3 CTAs/SM.
// R13 mainloop (best known).
// ---------------------------------------------------------------------------
#define BM 128
#define BN 128
#define BK 64
#define PADK 72                        // halves per smem row (64 + 8 pad)
#define TILEA (128 * PADK * 2)         // 18432 B
#define STAGEB (2 * TILEA)             // 36864 B
#define GEMM_SMEM (2 * STAGEB)         // 73728 B (2 stages)

#define GEMM_MAINLOOP64(Aptr, Bptr, Kval)                                        \
    const int NCH = (Kval) >> 6;                                                 \
    auto load_chunk = [&](int cc, int stg) {                                     \
        const uint32_t sb = sbase + stg * STAGEB;                                \
        const int kc = cc * BK;                                                  \
        _Pragma("unroll")                                                        \
        for (int i = 0; i < 8; i++) {                                            \
            int op = tid + i * 128;       /* 0..1023 */                          \
            int row = op >> 3;                                                   \
            int ck = op & 7;                                                     \
            uint32_t soff = (uint32_t)(row * PADK * 2 + ck * 16);                \
            cp16(sb + soff, (Aptr) + (size_t)(m0 + row) * (Kval) + kc + ck * 8); \
            cp16(sb + TILEA + soff,                                              \
                 (Bptr) + (size_t)(n0 + row) * (Kval) + kc + ck * 8);            \
        }                                                                        \
        cp_commit();                                                             \
    };                                                                           \
    load_chunk(0, 0);                                                            \
    const int a_row = (lane & 15);                                               \
    const int a_col = ((lane >> 4) & 1) * 8;                                     \
    const int b_row = (lane & 7) + ((lane & 16) ? 8 : 0);                        \
    const int b_col = ((lane & 8) ? 8 : 0);                                      \
    for (int cch = 0; cch < NCH; cch++) {                                        \
        cp_wait<0>();                                                            \
        __syncthreads();                                                         \
        if (cch + 1 < NCH) load_chunk(cch + 1, (cch + 1) & 1);                   \
        const uint32_t sA = sbase + (cch & 1) * STAGEB;                          \
        const uint32_t sB = sA + TILEA;                                          \
        _Pragma("unroll")                                                        \
        for (int s = 0; s < 4; s++) {                                            \
            uint32_t af[16], bf[8];                                              \
            _Pragma("unroll")                                                    \
            for (int i = 0; i < 4; i++) {                                        \
                int row = wm * 64 + i * 16 + a_row;                              \
                ldsm4(&af[i * 4],                                                \
                      sA + (uint32_t)((row * PADK + s * 16 + a_col) * 2));       \
            }                                                                    \
            _Pragma("unroll")                                                    \
            for (int half = 0; half < 2; half++) {                               \
                _Pragma("unroll")                                                \
                for (int j2 = 0; j2 < 2; j2++) {                                 \
                    int row = wn * 64 + (half * 2 + j2) * 16 + b_row;            \
                    ldsm4(&bf[j2 * 4],                                           \
                          sB + (uint32_t)((row * PADK + s * 16 + b_col) * 2));   \
                }                                                                \
                _Pragma("unroll")                                                \
                for (int i = 0; i < 4; i++)                                      \
                    _Pragma("unroll")                                            \
                    for (int j = 0; j < 4; j++)                                  \
                        mma16816(c[i][half * 4 + j], &af[i * 4], &bf[j * 2]);    \
            }                                                                    \
        }                                                                        \
    }

// ---------------------------------------------------------------------------
// Plain GEMM: C[M,N] = A @ B^T, fp32 out (O-projection).
// ---------------------------------------------------------------------------
__global__ __launch_bounds__(128, 3)
void gemm_f16(const __half* __restrict__ Ah, const __half* __restrict__ Bh,
              float* __restrict__ C, int N, int K)
{
    extern __shared__ char smraw[];
    const uint32_t sbase = smem_u32(smraw);

    const int tid = threadIdx.x;
    const int wid = tid >> 5;
    const int lane = tid & 31;
    const int wm = wid >> 1;
    const int wn = wid & 1;
    const int m0 = blockIdx.y * BM;
    const int n0 = blockIdx.x * BN;

    float c[4][8][4];
#pragma unroll
    for (int i = 0; i < 4; i++)
#pragma unroll
        for (int j = 0; j < 8; j++)
#pragma unroll
            for (int q = 0; q < 4; q++) c[i][j][q] = 0.f;

    GEMM_MAINLOOP64(Ah, Bh, K)

    const int g = lane >> 2;
    const int tq = lane & 3;
#pragma unroll
    for (int i = 0; i < 4; i++) {
        int row0 = m0 + wm * 64 + i * 16 + g;
#pragma unroll
        for (int j = 0; j < 8; j++) {
            int col = n0 + wn * 64 + j * 8 + tq * 2;
            float2 v0 = {c[i][j][0], c[i][j][1]};
            float2 v1 = {c[i][j][2], c[i][j][3]};
            *(float2*)&C[(size_t)row0 * N + col] = v0;
            *(float2*)&C[(size_t)(row0 + 8) * N + col] = v1;
        }
    }
}

// ---------------------------------------------------------------------------
// QKV GEMM (head-group variant) with fused RoPE + fp16 head-major epilogue.
// grid: (heads_in_group, TOK/BM, 3 regions). hbase selects the head group.
// Q scale includes log2(e) so attention can use exp2.
// ---------------------------------------------------------------------------
#define SCPAD 132

__global__ __launch_bounds__(128, 3)
void gemm_qkv(const __half* __restrict__ Ah, const __half* __restrict__ Bh,
              const float2* __restrict__ rtab,
              __half* __restrict__ Qh, __half* __restrict__ Kh,
              __half* __restrict__ Vh, int hbase, int K)
{
    extern __shared__ char smraw[];
    const uint32_t sbase = smem_u32(smraw);

    const int tid = threadIdx.x;
    const int wid = tid >> 5;
    const int lane = tid & 31;
    const int wm = wid >> 1;
    const int wn = wid & 1;
    const int region = blockIdx.z;             // 0=q,1=k,2=v
    const int h = hbase + blockIdx.x;
    const int m0 = blockIdx.y * BM;
    const int n0 = region * HID + h * HD;

    float c[4][8][4];
#pragma unroll
    for (int i = 0; i < 4; i++)
#pragma unroll
        for (int j = 0; j < 8; j++)
#pragma unroll
            for (int q = 0; q < 4; q++) c[i][j][q] = 0.f;

    GEMM_MAINLOOP64(Ah, Bh, K)

    // ---- fused epilogue: stage fp32 tile in smem ----
    __syncthreads();
    float* sc = (float*)smraw;       // [128][SCPAD]

    const int g = lane >> 2;
    const int tq = lane & 3;
#pragma unroll
    for (int i = 0; i < 4; i++) {
        int r0 = wm * 64 + i * 16 + g;
#pragma unroll
        for (int j = 0; j < 8; j++) {
            int col = wn * 64 + j * 8 + tq * 2;
            *(float2*)&sc[r0 * SCPAD + col] = make_float2(c[i][j][0], c[i][j][1]);
            *(float2*)&sc[(r0 + 8) * SCPAD + col] = make_float2(c[i][j][2], c[i][j][3]);
        }
    }
    __syncthreads();

    // Q scale folds 1/sqrt(128) * log2(e) so attention uses exp2 directly.
    const float qscale = (region == 0)
        ? 0.08838834764831845f * 1.4426950408889634f : 1.0f;
    __half* outp = (region == 0) ? Qh : (region == 1 ? Kh : Vh);

    const int i0 = (tid & 15) * 4;
    const int rbase = tid >> 4;

#pragma unroll 1
    for (int rr = 0; rr < 16; rr++) {
        int row = rbase + rr * 8;
        int t = m0 + row;
        int bb = t >> 11;
        int ss = t & 2047;
        __half* dp = outp + ((size_t)(bb * NH + h) * S_SZ + ss) * HD;

        float r1v[4], r2v[4];
        if (region < 2) {
            const float2* tp = rtab + (size_t)t * 64 + i0;
#pragma unroll
            for (int ii = 0; ii < 4; ii++) {
                int i = i0 + ii;
                float x1 = sc[row * SCPAD + i];
                float x2 = sc[row * SCPAD + i + 64];
                float2 csn = tp[ii];
                r1v[ii] = (x1 * csn.x - x2 * csn.y) * qscale;
                r2v[ii] = (x2 * csn.x + x1 * csn.y) * qscale;
            }
        } else {
#pragma unroll
            for (int ii = 0; ii < 4; ii++) {
                int i = i0 + ii;
                r1v[ii] = sc[row * SCPAD + i];
                r2v[ii] = sc[row * SCPAD + i + 64];
            }
        }
        *(uint32_t*)&dp[i0]     = packh2(r1v[0], r1v[1]);
        *(uint32_t*)&dp[i0 + 2] = packh2(r1v[2], r1v[3]);
        *(uint32_t*)&dp[i0 + 64] = packh2(r2v[0], r2v[1]);
        *(uint32_t*)&dp[i0 + 66] = packh2(r2v[2], r2v[3]);
    }
}

// ---------------------------------------------------------------------------
// HMMA flash attention (head-group variant), causal. Br=128, Bc=128.
// grid: (16 q-blocks, 2 batches, heads_in_group). Scores arrive pre-scaled
// by log2(e) via Q, so softmax uses exp2f.
// ---------------------------------------------------------------------------
#define ATT_PAD 136
#define KVROWB (ATT_PAD * 2)            // 272 bytes
#define KTILE2 (128 * KVROWB)           // 34816
#define ASTG (2 * KTILE2)               // K, V = 69632
#define ATT_SMEM (2 * ASTG)             // 139264

__global__ __launch_bounds__(256, 1)
void flash_attn_hmma(const __half* __restrict__ Qh, const __half* __restrict__ Kh,
                     const __half* __restrict__ Vh, __half* __restrict__ Xh, int hbase)
{
    extern __shared__ char smraw[];
    const uint32_t sbase = smem_u32(smraw);

    const int tid = threadIdx.x;
    const int wid = tid >> 5;
    const int lane = tid & 31;
    const int g = lane >> 2;
    const int tq = lane & 3;

    const int qb = 15 - (int)blockIdx.x;
    const int b = blockIdx.y;
    const int h = hbase + blockIdx.z;
    const int bh = b * NH + h;
    const size_t hb = (size_t)bh * S_SZ * HD;
    const int row0 = qb * 128;
    const int wr = wid * 16;
    const int nkb = qb + 1;

    uint32_t qhf[8][4];
    {
        const __half* qsrc = Qh + hb + (size_t)row0 * HD;
#pragma unroll
        for (int i = 0; i < 8; i++) {
            int op = tid + i * 256;
            int r = op >> 4;
            int ck = op & 15;
            cp16(sbase + (uint32_t)(r * KVROWB + ck * 16), qsrc + (size_t)r * HD + ck * 8);
        }
        cp_commit();
        cp_wait<0>();
        __syncthreads();
#pragma unroll
        for (int ks = 0; ks < 8; ks++) {
            uint32_t off = (uint32_t)((wr + (lane & 15)) * KVROWB +
                                      (ks * 16 + ((lane >> 4) << 3)) * 2);
            ldsm4(qhf[ks], sbase + off);
        }
        __syncthreads();
    }

    float o[16][4];
#pragma unroll
    for (int j = 0; j < 16; j++)
#pragma unroll
        for (int q = 0; q < 4; q++) o[j][q] = 0.f;
    float m_old0 = -1e30f, m_old1 = -1e30f, l0 = 0.f, l1 = 0.f;

    auto kvload = [&](int kb, int stg) {
        const uint32_t sb = sbase + stg * ASTG;
        const size_t src0 = hb + (size_t)kb * 128 * HD;
#pragma unroll
        for (int i = 0; i < 8; i++) {
            int op = tid + i * 256;
            int r = op >> 4;
            int ck = op & 15;
            uint32_t soff = (uint32_t)(r * KVROWB + ck * 16);
            size_t goff = src0 + (size_t)r * HD + ck * 8;
            cp16(sb + soff, Kh + goff);
            cp16(sb + KTILE2 + soff, Vh + goff);
        }
        cp_commit();
    };

    kvload(0, 0);

    const int r_g = row0 + wr + g;

    for (int kb = 0; kb < nkb; kb++) {
        if (kb + 1 < nkb) kvload(kb + 1, (kb + 1) & 1);
        else cp_commit();
        cp_wait<1>();
        __syncthreads();

        const uint32_t sK = sbase + (kb & 1) * ASTG;
        const uint32_t sV = sK + KTILE2;

        float s[16][4];
#pragma unroll
        for (int j = 0; j < 16; j++)
#pragma unroll
            for (int q = 0; q < 4; q++) s[j][q] = 0.f;

#pragma unroll
        for (int ks = 0; ks < 8; ks++) {
            uint32_t bk[32];
#pragma unroll
            for (int j2 = 0; j2 < 8; j2++) {
                int r = j2 * 16 + (lane & 7) + ((lane & 16) ? 8 : 0);
                uint32_t off = (uint32_t)(r * KVROWB + (ks * 16 + ((lane & 8) ? 8 : 0)) * 2);
                ldsm4(&bk[j2 * 4], sK + off);
            }
#pragma unroll
            for (int j = 0; j < 16; j++) mma16816(s[j], qhf[ks], &bk[j * 2]);
        }

        const int kv0 = kb * 128;
        if (kv0 + 127 > row0 + wr) {
#pragma unroll
            for (int j = 0; j < 16; j++) {
                int cc = kv0 + j * 8 + 2 * tq;
                if (cc > r_g) s[j][0] = -1e30f;
                if (cc + 1 > r_g) s[j][1] = -1e30f;
                if (cc > r_g + 8) s[j][2] = -1e30f;
                if (cc + 1 > r_g + 8) s[j][3] = -1e30f;
            }
        }

        float mx0 = -1e30f, mx1 = -1e30f;
#pragma unroll
        for (int j = 0; j < 16; j++) {
            mx0 = fmaxf(mx0, fmaxf(s[j][0], s[j][1]));
            mx1 = fmaxf(mx1, fmaxf(s[j][2], s[j][3]));
        }
        mx0 = fmaxf(mx0, __shfl_xor_sync(0xffffffffu, mx0, 1));
        mx0 = fmaxf(mx0, __shfl_xor_sync(0xffffffffu, mx0, 2));
        mx1 = fmaxf(mx1, __shfl_xor_sync(0xffffffffu, mx1, 1));
        mx1 = fmaxf(mx1, __shfl_xor_sync(0xffffffffu, mx1, 2));

        float mn0 = fmaxf(m_old0, mx0);
        float mn1 = fmaxf(m_old1, mx1);
        float a0 = exp2f(m_old0 - mn0);
        float a1 = exp2f(m_old1 - mn1);

        float sum0 = 0.f, sum1 = 0.f;
        uint32_t pa[8][4];
#pragma unroll
        for (int ks = 0; ks < 8; ks++) {
            float p00 = exp2f(s[2 * ks][0] - mn0);
            float p01 = exp2f(s[2 * ks][1] - mn0);
            float p02 = exp2f(s[2 * ks][2] - mn1);
            float p03 = exp2f(s[2 * ks][3] - mn1);
            float p10 = exp2f(s[2 * ks + 1][0] - mn0);
            float p11 = exp2f(s[2 * ks + 1][1] - mn0);
            float p12 = exp2f(s[2 * ks + 1][2] - mn1);
            float p13 = exp2f(s[2 * ks + 1][3] - mn1);
            sum0 += p00 + p01 + p10 + p11;
            sum1 += p02 + p03 + p12 + p13;
            pa[ks][0] = packh2(p00, p01);
            pa[ks][1] = packh2(p02, p03);
            pa[ks][2] = packh2(p10, p11);
            pa[ks][3] = packh2(p12, p13);
        }
        sum0 += __shfl_xor_sync(0xffffffffu, sum0, 1);
        sum0 += __shfl_xor_sync(0xffffffffu, sum0, 2);
        sum1 += __shfl_xor_sync(0xffffffffu, sum1, 1);
        sum1 += __shfl_xor_sync(0xffffffffu, sum1, 2);

        l0 = l0 * a0 + sum0;
        l1 = l1 * a1 + sum1;
        m_old0 = mn0;
        m_old1 = mn1;

#pragma unroll
        for (int j = 0; j < 16; j++) {
            o[j][0] *= a0; o[j][1] *= a0;
            o[j][2] *= a1; o[j][3] *= a1;
        }

#pragma unroll
        for (int ks = 0; ks < 8; ks++) {
#pragma unroll
            for (int jj = 0; jj < 8; jj++) {
                int krow = ks * 16 + (lane & 15);
                uint32_t off = (uint32_t)(krow * KVROWB + (jj * 16 + ((lane & 16) ? 8 : 0)) * 2);
                uint32_t bv[4];
                ldsm4t(bv, sV + off);
                mma16816(o[jj * 2], pa[ks], &bv[0]);
                mma16816(o[jj * 2 + 1], pa[ks], &bv[2]);
            }
        }
        __syncthreads();
    }

    const float il0 = 1.f / l0;
    const float il1 = 1.f / l1;
    const int tok0 = b * S_SZ + row0 + wr;
#pragma unroll
    for (int j = 0; j < 16; j++) {
        int col = h * HD + j * 8 + 2 * tq;
        size_t i0 = (size_t)(tok0 + g) * HID + col;
        size_t i1 = (size_t)(tok0 + g + 8) * HID + col;
        *(uint32_t*)&Xh[i0] = packh2(o[j][0] * il0, o[j][1] * il0);
        *(uint32_t*)&Xh[i1] = packh2(o[j][2] * il1, o[j][3] * il1);
    }
}

// ---------------------------------------------------------------------------
// Launch — head-group pipelining: [gemmQKV(g) -> attn(g)] on 2 streams,
// W_o conversion on a third. Join before O-projection.
// ---------------------------------------------------------------------------
extern "C" void kernel_launch(void* const* d_in, const int* in_sizes, int n_in,
                              void* d_out, int out_size)
{
    const float* hidden = (const float*)d_in[0];
    const int* positions = (const int*)d_in[1];
    const float* W_pack = (const float*)d_in[2];
    const float* W_o = (const float*)d_in[3];
    float* out = (float*)d_out;

    void* v_ah; cudaGetSymbolAddress(&v_ah, g_Ah);
    void* v_wp; cudaGetSymbolAddress(&v_wp, g_Wp);
    void* v_wo; cudaGetSymbolAddress(&v_wo, g_Wo);
    void* v_xh; cudaGetSymbolAddress(&v_xh, g_Xh);
    void* v_qh; cudaGetSymbolAddress(&v_qh, g_Qh);
    void* v_kh; cudaGetSymbolAddress(&v_kh, g_Kh);
    void* v_vh; cudaGetSymbolAddress(&v_vh, g_Vh);
    void* v_rt; cudaGetSymbolAddress(&v_rt, g_rope);

    cudaFuncSetAttribute(gemm_f16, cudaFuncAttributeMaxDynamicSharedMemorySize, GEMM_SMEM);
    cudaFuncSetAttribute(gemm_qkv, cudaFuncAttributeMaxDynamicSharedMemorySize, GEMM_SMEM);
    cudaFuncSetAttribute(flash_attn_hmma, cudaFuncAttributeMaxDynamicSharedMemorySize, ATT_SMEM);

    cudaStream_t s2, s3;
    cudaEvent_t evFork, evPrep, evWo, evA1;
    cudaStreamCreateWithFlags(&s2, cudaStreamNonBlocking);
    cudaStreamCreateWithFlags(&s3, cudaStreamNonBlocking);
    cudaEventCreateWithFlags(&evFork, cudaEventDisableTiming);
    cudaEventCreateWithFlags(&evPrep, cudaEventDisableTiming);
    cudaEventCreateWithFlags(&evWo, cudaEventDisableTiming);
    cudaEventCreateWithFlags(&evA1, cudaEventDisableTiming);

    // Fork s3: W_o conversion (needed only by O-proj)
    cudaEventRecord(evFork, 0);
    cudaStreamWaitEvent(s3, evFork, 0);
    {
        int o8 = HID * HID / 8;
        conv_f16<<<(o8 + 255) / 256, 256, 0, s3>>>(W_o, (__half*)v_wo, o8);
    }
    cudaEventRecord(evWo, s3);

    // Main stream: prep inputs for QKV GEMM
    {
        int n8 = TOK * HID / 8;
        conv_f16<<<(n8 + 255) / 256, 256>>>(hidden, (__half*)v_ah, n8);
        int w8 = PROJ3 * HID / 8;
        conv_f16<<<(w8 + 255) / 256, 256>>>(W_pack, (__half*)v_wp, w8);
        rope_table<<<TOK * 64 / 256, 256>>>(positions, (float2*)v_rt);
    }
    cudaEventRecord(evPrep, 0);

    // Stream s2: head group 1 (heads 16..31): QKV GEMM then attention
    cudaStreamWaitEvent(s2, evPrep, 0);
    {
        dim3 grid(16, TOK / BM, 3);    // 16 heads x 32 row-tiles x 3 regions
        gemm_qkv<<<grid, 128, GEMM_SMEM, s2>>>((const __half*)v_ah, (const __half*)v_wp,
                                               (const float2*)v_rt,
                                               (__half*)v_qh, (__half*)v_kh, (__half*)v_vh,
                                               16, HID);
        dim3 agrid(16, B_SZ, 16);
        flash_attn_hmma<<<agrid, 256, ATT_SMEM, s2>>>((const __half*)v_qh, (const __half*)v_kh,
                                                      (const __half*)v_vh, (__half*)v_xh, 16);
    }
    cudaEventRecord(evA1, s2);

    // Main stream: head group 0 (heads 0..15): QKV GEMM then attention
    {
        dim3 grid(16, TOK / BM, 3);
        gemm_qkv<<<grid, 128, GEMM_SMEM>>>((const __half*)v_ah, (const __half*)v_wp,
                                           (const float2*)v_rt,
                                           (__half*)v_qh, (__half*)v_kh, (__half*)v_vh,
                                           0, HID);
        dim3 agrid(16, B_SZ, 16);
        flash_attn_hmma<<<agrid, 256, ATT_SMEM>>>((const __half*)v_qh, (const __half*)v_kh,
                                                  (const __half*)v_vh, (__half*)v_xh, 0);
    }

    // Join both side streams before the O-projection
    cudaStreamWaitEvent(0, evA1, 0);
    cudaStreamWaitEvent(0, evWo, 0);

    // O-projection: out = attn @ W_o^T
    {
        dim3 grid(HID / BN, TOK / BM);  // 32 x 32
        gemm_f16<<<grid, 128, GEMM_SMEM>>>((const __half*)v_xh, (const __half*)v_wo,
                                           out, HID, HID);
    }

    cudaStreamDestroy(s2);
    cudaStreamDestroy(s3);
    cudaEventDestroy(evFork);
    cudaEventDestroy(evPrep);
    cudaEventDestroy(evWo);
    cudaEventDestroy(evA1);
}